// round 2
// baseline (speedup 1.0000x reference)
#include <cuda_runtime.h>
#include <cuda_bf16.h>
#include <cstdint>
#include <cstddef>

// ---------------------------------------------------------------------------
// WindowAttention (Swin-style): B_=4096 windows, N=49, C=384, H=12, hd=32
//   qkv = x @ qkv_w^T + qkv_b
//   attn = softmax(scale*q@k^T + bias[rel_index] + mask)
//   out = (attn @ v) @ proj_w^T + proj_b
// Round 2: fix inline-asm operand bug in to_tf32 (ICE); same structure as R1.
// ---------------------------------------------------------------------------

#define B_WIN   4096
#define N_TOK   49
#define DIM     384
#define H_HEADS 12
#define HD      32
#define T_TOT   (B_WIN * N_TOK)      // 200704 tokens
#define NW_MASK 64

// scratch (static device globals; no allocations allowed)
__device__ float g_qkv[(size_t)T_TOT * 3 * DIM];   // (T, 1152)
__device__ float g_ao [(size_t)T_TOT * DIM];       // (T, 384) attention output
__device__ float g_bias[H_HEADS * N_TOK * N_TOK];  // (H, 49, 49) gathered bias

// ---------------------------------------------------------------------------
// helpers
// ---------------------------------------------------------------------------
__device__ __forceinline__ float to_tf32(float x) {
    asm("cvt.rna.tf32.f32 %0, %0;" : "+f"(x));
    return x;
}

__device__ __forceinline__ void mma_tf32_16x8x8(float d[4], const uint32_t a[4],
                                                const uint32_t b[2]) {
    asm volatile(
        "mma.sync.aligned.m16n8k8.row.col.f32.tf32.tf32.f32 "
        "{%0,%1,%2,%3}, {%4,%5,%6,%7}, {%8,%9}, {%0,%1,%2,%3};\n"
        : "+f"(d[0]), "+f"(d[1]), "+f"(d[2]), "+f"(d[3])
        : "r"(a[0]), "r"(a[1]), "r"(a[2]), "r"(a[3]), "r"(b[0]), "r"(b[1]));
}

// ---------------------------------------------------------------------------
// Kernel 0: gather relative-position bias -> (H, N, N)
// ---------------------------------------------------------------------------
__global__ void bias_gather_kernel(const float* __restrict__ bias_table,
                                   const int* __restrict__ rel_index) {
    int idx = blockIdx.x * blockDim.x + threadIdx.x;
    if (idx < H_HEADS * N_TOK * N_TOK) {
        int h  = idx / (N_TOK * N_TOK);
        int nm = idx - h * (N_TOK * N_TOK);
        g_bias[idx] = bias_table[rel_index[nm] * H_HEADS + h];
    }
}

// ---------------------------------------------------------------------------
// Kernel 1/3: TF32 GEMM  C[m,n] = sum_k A[m,k]*B[n,k] + bias[n]
//   A: (M,K) row-major, B: (N,K) row-major, C: (M,N) row-major
//   BM=128, BN=64, BK=32, 256 threads (8 warps, 4x2), warp tile 32x32
//   M % 128 == 0, N % 64 == 0, K % 32 == 0 (holds for all our shapes)
// ---------------------------------------------------------------------------
#define GBM 128
#define GBN 64
#define GBK 32
#define GPAD 4
#define GSTRIDE (GBK + GPAD)   // 36 words: frag LDS conflict-free, 16B-aligned stores

__global__ __launch_bounds__(256)
void gemm_tf32_kernel(const float* __restrict__ A, const float* __restrict__ B,
                      const float* __restrict__ bias, float* __restrict__ C,
                      int M, int N, int K) {
    __shared__ float As[GBM * GSTRIDE];
    __shared__ float Bs[GBN * GSTRIDE];

    const int tid  = threadIdx.x;
    const int lane = tid & 31;
    const int warp = tid >> 5;
    const int wm   = warp >> 1;        // 0..3
    const int wn   = warp & 1;         // 0..1
    const int bm   = blockIdx.y * GBM;
    const int bn   = blockIdx.x * GBN;
    const int r4   = lane >> 2;        // 0..7
    const int c4   = lane & 3;         // 0..3

    float acc[2][4][4];
    #pragma unroll
    for (int mt = 0; mt < 2; mt++)
        #pragma unroll
        for (int nt = 0; nt < 4; nt++)
            #pragma unroll
            for (int i = 0; i < 4; i++) acc[mt][nt][i] = 0.f;

    for (int kt = 0; kt < K; kt += GBK) {
        // --- load A tile 128x32 (1024 float4, 4/thread), convert to tf32 ---
        #pragma unroll
        for (int i = 0; i < 4; i++) {
            int idx = tid + i * 256;
            int row = idx >> 3;
            int col = (idx & 7) * 4;
            float4 v = *(const float4*)(A + (size_t)(bm + row) * K + kt + col);
            v.x = to_tf32(v.x); v.y = to_tf32(v.y);
            v.z = to_tf32(v.z); v.w = to_tf32(v.w);
            *(float4*)&As[row * GSTRIDE + col] = v;
        }
        // --- load B tile 64x32 (512 float4, 2/thread) ---
        #pragma unroll
        for (int i = 0; i < 2; i++) {
            int idx = tid + i * 256;
            int row = idx >> 3;
            int col = (idx & 7) * 4;
            float4 v = *(const float4*)(B + (size_t)(bn + row) * K + kt + col);
            v.x = to_tf32(v.x); v.y = to_tf32(v.y);
            v.z = to_tf32(v.z); v.w = to_tf32(v.w);
            *(float4*)&Bs[row * GSTRIDE + col] = v;
        }
        __syncthreads();

        #pragma unroll
        for (int k8 = 0; k8 < GBK; k8 += 8) {
            uint32_t af[2][4];
            uint32_t bf[4][2];
            #pragma unroll
            for (int mt = 0; mt < 2; mt++) {
                int am = wm * 32 + mt * 16;
                af[mt][0] = __float_as_uint(As[(am + r4    ) * GSTRIDE + k8 + c4    ]);
                af[mt][1] = __float_as_uint(As[(am + r4 + 8) * GSTRIDE + k8 + c4    ]);
                af[mt][2] = __float_as_uint(As[(am + r4    ) * GSTRIDE + k8 + c4 + 4]);
                af[mt][3] = __float_as_uint(As[(am + r4 + 8) * GSTRIDE + k8 + c4 + 4]);
            }
            #pragma unroll
            for (int nt = 0; nt < 4; nt++) {
                int bb = wn * 32 + nt * 8;
                bf[nt][0] = __float_as_uint(Bs[(bb + r4) * GSTRIDE + k8 + c4    ]);
                bf[nt][1] = __float_as_uint(Bs[(bb + r4) * GSTRIDE + k8 + c4 + 4]);
            }
            #pragma unroll
            for (int mt = 0; mt < 2; mt++)
                #pragma unroll
                for (int nt = 0; nt < 4; nt++)
                    mma_tf32_16x8x8(acc[mt][nt], af[mt], bf[nt]);
        }
        __syncthreads();
    }

    // --- epilogue: add bias, store fp32 ---
    #pragma unroll
    for (int mt = 0; mt < 2; mt++) {
        int row0 = bm + wm * 32 + mt * 16 + r4;
        #pragma unroll
        for (int nt = 0; nt < 4; nt++) {
            int col = bn + wn * 32 + nt * 8 + 2 * c4;
            float b0 = bias[col], b1 = bias[col + 1];
            float2 v01 = make_float2(acc[mt][nt][0] + b0, acc[mt][nt][1] + b1);
            float2 v23 = make_float2(acc[mt][nt][2] + b0, acc[mt][nt][3] + b1);
            *(float2*)(C + (size_t)row0 * N + col)       = v01;
            *(float2*)(C + (size_t)(row0 + 8) * N + col) = v23;
        }
    }
}

// ---------------------------------------------------------------------------
// Kernel 2: fused attention per (window, head)
//   grid (H=12, B_=4096), 256 threads
// ---------------------------------------------------------------------------
__global__ __launch_bounds__(256)
void attn_kernel(const float* __restrict__ mask) {
    __shared__ float qs[N_TOK][HD + 1];   // pad 33: conflict-free
    __shared__ float ks[N_TOK][HD + 1];
    __shared__ float vs[N_TOK][HD + 1];
    __shared__ float Ss[N_TOK][N_TOK + 1];

    const int h   = blockIdx.x;
    const int b   = blockIdx.y;
    const int tid = threadIdx.x;
    const int lane = tid & 31;
    const int warp = tid >> 5;
    const float scale = 0.1767766952966369f;   // 32^-0.5

    // --- load q, k, v for this (window, head): coalesced 32-float rows ---
    const float* base = g_qkv + (size_t)b * N_TOK * (3 * DIM) + h * HD;
    for (int idx = tid; idx < N_TOK * HD; idx += 256) {
        int n = idx >> 5;
        int d = idx & 31;
        const float* rowp = base + (size_t)n * (3 * DIM) + d;
        qs[n][d] = rowp[0];
        ks[n][d] = rowp[DIM];
        vs[n][d] = rowp[2 * DIM];
    }
    __syncthreads();

    // --- S = scale*q@k^T + bias + mask ---
    const float* mrow = mask   + (size_t)(b & (NW_MASK - 1)) * N_TOK * N_TOK;
    const float* brow = g_bias + (size_t)h * N_TOK * N_TOK;
    for (int idx = tid; idx < N_TOK * N_TOK; idx += 256) {
        int n = idx / N_TOK;
        int m = idx - n * N_TOK;
        float a = 0.f;
        #pragma unroll
        for (int d = 0; d < HD; d++) a += qs[n][d] * ks[m][d];
        Ss[n][m] = a * scale + brow[idx] + mrow[idx];
    }
    __syncthreads();

    // --- softmax: one warp per row ---
    for (int rr = warp; rr < N_TOK; rr += 8) {
        float x0 = Ss[rr][lane];
        float x1 = (lane + 32 < N_TOK) ? Ss[rr][lane + 32] : -__int_as_float(0x7f800000);
        float mx = fmaxf(x0, x1);
        #pragma unroll
        for (int o = 16; o > 0; o >>= 1)
            mx = fmaxf(mx, __shfl_xor_sync(0xffffffffu, mx, o));
        float e0 = __expf(x0 - mx);
        float e1 = (lane + 32 < N_TOK) ? __expf(x1 - mx) : 0.f;
        float s = e0 + e1;
        #pragma unroll
        for (int o = 16; o > 0; o >>= 1)
            s += __shfl_xor_sync(0xffffffffu, s, o);
        float inv = __frcp_rn(s);
        Ss[rr][lane] = e0 * inv;
        if (lane + 32 < N_TOK) Ss[rr][lane + 32] = e1 * inv;
    }
    __syncthreads();

    // --- O = P @ v, scatter to (B_, N, C) with col offset h*32 ---
    float* aob = g_ao + (size_t)b * N_TOK * DIM + h * HD;
    for (int idx = tid; idx < N_TOK * HD; idx += 256) {
        int n = idx >> 5;
        int d = idx & 31;
        float a = 0.f;
        #pragma unroll
        for (int m = 0; m < N_TOK; m++) a += Ss[n][m] * vs[m][d];
        aob[(size_t)n * DIM + d] = a;
    }
}

// ---------------------------------------------------------------------------
// launch
// ---------------------------------------------------------------------------
extern "C" void kernel_launch(void* const* d_in, const int* in_sizes, int n_in,
                              void* d_out, int out_size) {
    const float* x          = (const float*)d_in[0];
    const float* mask       = (const float*)d_in[1];
    const float* qkv_w      = (const float*)d_in[2];
    const float* qkv_b      = (const float*)d_in[3];
    const float* proj_w     = (const float*)d_in[4];
    const float* proj_b     = (const float*)d_in[5];
    const float* bias_table = (const float*)d_in[6];
    const int*   rel_index  = (const int*)d_in[7];
    float* out = (float*)d_out;

    void* p_qkv = nullptr;
    void* p_ao  = nullptr;
    cudaGetSymbolAddress(&p_qkv, g_qkv);
    cudaGetSymbolAddress(&p_ao,  g_ao);
    float* qkv = (float*)p_qkv;
    float* ao  = (float*)p_ao;

    // 0) gather bias (H,N,N)
    {
        int n = H_HEADS * N_TOK * N_TOK;
        bias_gather_kernel<<<(n + 255) / 256, 256>>>(bias_table, rel_index);
    }
    // 1) QKV GEMM: (T,384) @ (1152,384)^T -> (T,1152)
    {
        dim3 grid((3 * DIM) / GBN, T_TOT / GBM);
        gemm_tf32_kernel<<<grid, 256>>>(x, qkv_w, qkv_b, qkv, T_TOT, 3 * DIM, DIM);
    }
    // 2) fused attention
    {
        dim3 grid(H_HEADS, B_WIN);
        attn_kernel<<<grid, 256>>>(mask);
    }
    // 3) proj GEMM: (T,384) @ (384,384)^T -> (T,384)
    {
        dim3 grid(DIM / GBN, T_TOT / GBM);
        gemm_tf32_kernel<<<grid, 256>>>(ao, proj_w, proj_b, out, T_TOT, DIM, DIM);
    }
}

// round 3
// speedup vs baseline: 1.2111x; 1.2111x over previous
#include <cuda_runtime.h>
#include <cuda_bf16.h>
#include <cstdint>
#include <cstddef>

// ---------------------------------------------------------------------------
// WindowAttention (Swin-style): B_=4096 windows, N=49, C=384, H=12, hd=32
// Round 3: attention on tensor cores (tf32 mma for QK^T and PV).
// ---------------------------------------------------------------------------

#define B_WIN   4096
#define N_TOK   49
#define DIM     384
#define H_HEADS 12
#define HD      32
#define T_TOT   (B_WIN * N_TOK)      // 200704 tokens
#define NW_MASK 64

// scratch (static device globals; no allocations allowed)
__device__ float g_qkv[(size_t)T_TOT * 3 * DIM];   // (T, 1152)
__device__ float g_ao [(size_t)T_TOT * DIM];       // (T, 384) attention output
__device__ float g_bias[H_HEADS * N_TOK * N_TOK];  // (H, 49, 49) gathered bias

// ---------------------------------------------------------------------------
// helpers
// ---------------------------------------------------------------------------
__device__ __forceinline__ float to_tf32(float x) {
    asm("cvt.rna.tf32.f32 %0, %0;" : "+f"(x));
    return x;
}

__device__ __forceinline__ void mma_tf32_16x8x8(float d[4], const uint32_t a[4],
                                                const uint32_t b[2]) {
    asm volatile(
        "mma.sync.aligned.m16n8k8.row.col.f32.tf32.tf32.f32 "
        "{%0,%1,%2,%3}, {%4,%5,%6,%7}, {%8,%9}, {%0,%1,%2,%3};\n"
        : "+f"(d[0]), "+f"(d[1]), "+f"(d[2]), "+f"(d[3])
        : "r"(a[0]), "r"(a[1]), "r"(a[2]), "r"(a[3]), "r"(b[0]), "r"(b[1]));
}

// ---------------------------------------------------------------------------
// Kernel 0: gather relative-position bias -> (H, N, N)
// ---------------------------------------------------------------------------
__global__ void bias_gather_kernel(const float* __restrict__ bias_table,
                                   const int* __restrict__ rel_index) {
    int idx = blockIdx.x * blockDim.x + threadIdx.x;
    if (idx < H_HEADS * N_TOK * N_TOK) {
        int h  = idx / (N_TOK * N_TOK);
        int nm = idx - h * (N_TOK * N_TOK);
        g_bias[idx] = bias_table[rel_index[nm] * H_HEADS + h];
    }
}

// ---------------------------------------------------------------------------
// Kernel 1/3: TF32 GEMM  C[m,n] = sum_k A[m,k]*B[n,k] + bias[n]
//   BM=128, BN=64, BK=32, 256 threads (8 warps, 4x2), warp tile 32x32
// ---------------------------------------------------------------------------
#define GBM 128
#define GBN 64
#define GBK 32
#define GPAD 4
#define GSTRIDE (GBK + GPAD)   // 36

__global__ __launch_bounds__(256)
void gemm_tf32_kernel(const float* __restrict__ A, const float* __restrict__ B,
                      const float* __restrict__ bias, float* __restrict__ C,
                      int M, int N, int K) {
    __shared__ float As[GBM * GSTRIDE];
    __shared__ float Bs[GBN * GSTRIDE];

    const int tid  = threadIdx.x;
    const int lane = tid & 31;
    const int warp = tid >> 5;
    const int wm   = warp >> 1;
    const int wn   = warp & 1;
    const int bm   = blockIdx.y * GBM;
    const int bn   = blockIdx.x * GBN;
    const int r4   = lane >> 2;
    const int c4   = lane & 3;

    float acc[2][4][4];
    #pragma unroll
    for (int mt = 0; mt < 2; mt++)
        #pragma unroll
        for (int nt = 0; nt < 4; nt++)
            #pragma unroll
            for (int i = 0; i < 4; i++) acc[mt][nt][i] = 0.f;

    for (int kt = 0; kt < K; kt += GBK) {
        #pragma unroll
        for (int i = 0; i < 4; i++) {
            int idx = tid + i * 256;
            int row = idx >> 3;
            int col = (idx & 7) * 4;
            float4 v = *(const float4*)(A + (size_t)(bm + row) * K + kt + col);
            v.x = to_tf32(v.x); v.y = to_tf32(v.y);
            v.z = to_tf32(v.z); v.w = to_tf32(v.w);
            *(float4*)&As[row * GSTRIDE + col] = v;
        }
        #pragma unroll
        for (int i = 0; i < 2; i++) {
            int idx = tid + i * 256;
            int row = idx >> 3;
            int col = (idx & 7) * 4;
            float4 v = *(const float4*)(B + (size_t)(bn + row) * K + kt + col);
            v.x = to_tf32(v.x); v.y = to_tf32(v.y);
            v.z = to_tf32(v.z); v.w = to_tf32(v.w);
            *(float4*)&Bs[row * GSTRIDE + col] = v;
        }
        __syncthreads();

        #pragma unroll
        for (int k8 = 0; k8 < GBK; k8 += 8) {
            uint32_t af[2][4];
            uint32_t bf[4][2];
            #pragma unroll
            for (int mt = 0; mt < 2; mt++) {
                int am = wm * 32 + mt * 16;
                af[mt][0] = __float_as_uint(As[(am + r4    ) * GSTRIDE + k8 + c4    ]);
                af[mt][1] = __float_as_uint(As[(am + r4 + 8) * GSTRIDE + k8 + c4    ]);
                af[mt][2] = __float_as_uint(As[(am + r4    ) * GSTRIDE + k8 + c4 + 4]);
                af[mt][3] = __float_as_uint(As[(am + r4 + 8) * GSTRIDE + k8 + c4 + 4]);
            }
            #pragma unroll
            for (int nt = 0; nt < 4; nt++) {
                int bb = wn * 32 + nt * 8;
                bf[nt][0] = __float_as_uint(Bs[(bb + r4) * GSTRIDE + k8 + c4    ]);
                bf[nt][1] = __float_as_uint(Bs[(bb + r4) * GSTRIDE + k8 + c4 + 4]);
            }
            #pragma unroll
            for (int mt = 0; mt < 2; mt++)
                #pragma unroll
                for (int nt = 0; nt < 4; nt++)
                    mma_tf32_16x8x8(acc[mt][nt], af[mt], bf[nt]);
        }
        __syncthreads();
    }

    #pragma unroll
    for (int mt = 0; mt < 2; mt++) {
        int row0 = bm + wm * 32 + mt * 16 + r4;
        #pragma unroll
        for (int nt = 0; nt < 4; nt++) {
            int col = bn + wn * 32 + nt * 8 + 2 * c4;
            float b0 = bias[col], b1 = bias[col + 1];
            float2 v01 = make_float2(acc[mt][nt][0] + b0, acc[mt][nt][1] + b1);
            float2 v23 = make_float2(acc[mt][nt][2] + b0, acc[mt][nt][3] + b1);
            *(float2*)(C + (size_t)row0 * N + col)       = v01;
            *(float2*)(C + (size_t)(row0 + 8) * N + col) = v23;
        }
    }
}

// ---------------------------------------------------------------------------
// Kernel 2: fused attention per (window, head) on tensor cores
//   grid (H=12, B_=4096), 128 threads (4 warps); warp w owns rows [16w,16w+16)
// ---------------------------------------------------------------------------
#define QS_STR 36     // 4*r4+c4 bank pattern: conflict-free frag loads
#define SS_STR 57     // 25*r4+c4: near conflict-free; 49..55 zero-padded K
#define NEG_INF (-__int_as_float(0x7f800000))

__global__ __launch_bounds__(128)
void attn_mma_kernel(const float* __restrict__ mask) {
    __shared__ float qs[64][QS_STR];   // q*scale, tf32  (rows 49..63 garbage, guarded)
    __shared__ float ks[56][QS_STR];   // k, tf32        (rows 49..55 garbage, guarded)
    __shared__ float vt[32][SS_STR];   // v transposed [d][m], cols 49..55 = 0
    __shared__ float Ss[64][SS_STR];   // scores / probs, cols 49..55 = 0

    const int h    = blockIdx.x;
    const int b    = blockIdx.y;
    const int tid  = threadIdx.x;
    const int lane = tid & 31;
    const int warp = tid >> 5;
    const int r4   = lane >> 2;
    const int c4   = lane & 3;
    const float scale = 0.1767766952966369f;   // 32^-0.5

    // zero the padded regions (whole arrays: cheap)
    for (int i = tid; i < 64 * SS_STR; i += 128) (&Ss[0][0])[i] = 0.f;
    for (int i = tid; i < 32 * SS_STR; i += 128) (&vt[0][0])[i] = 0.f;

    // load q,k,v for this (window, head); q pre-scaled; all tf32-rounded
    const float* base = g_qkv + (size_t)b * N_TOK * (3 * DIM) + h * HD;
    for (int idx = tid; idx < N_TOK * HD; idx += 128) {
        int n = idx >> 5;
        int d = idx & 31;
        const float* rp = base + (size_t)n * (3 * DIM) + d;
        qs[n][d] = to_tf32(rp[0] * scale);
        ks[n][d] = to_tf32(rp[DIM]);
        vt[d][n] = to_tf32(rp[2 * DIM]);
    }
    __syncthreads();

    // --- S = (q*scale) @ k^T via mma: 7 N-tiles x 4 K-steps per warp ---
    {
        float acc[7][4];
        #pragma unroll
        for (int nt = 0; nt < 7; nt++)
            #pragma unroll
            for (int i = 0; i < 4; i++) acc[nt][i] = 0.f;

        const int am = warp * 16;
        #pragma unroll
        for (int k8 = 0; k8 < 32; k8 += 8) {
            uint32_t af[4], bf[7][2];
            af[0] = __float_as_uint(qs[am + r4    ][k8 + c4    ]);
            af[1] = __float_as_uint(qs[am + r4 + 8][k8 + c4    ]);
            af[2] = __float_as_uint(qs[am + r4    ][k8 + c4 + 4]);
            af[3] = __float_as_uint(qs[am + r4 + 8][k8 + c4 + 4]);
            #pragma unroll
            for (int nt = 0; nt < 7; nt++) {
                bf[nt][0] = __float_as_uint(ks[nt * 8 + r4][k8 + c4    ]);
                bf[nt][1] = __float_as_uint(ks[nt * 8 + r4][k8 + c4 + 4]);
            }
            #pragma unroll
            for (int nt = 0; nt < 7; nt++)
                mma_tf32_16x8x8(acc[nt], af, bf[nt]);
        }
        // store (guarded: rows/cols < 49 only)
        const int n0 = am + r4, n1 = n0 + 8;
        #pragma unroll
        for (int nt = 0; nt < 7; nt++) {
            int col = nt * 8 + 2 * c4;
            if (col < N_TOK) {
                bool c1ok = (col + 1 < N_TOK);
                if (n0 < N_TOK) {
                    Ss[n0][col] = acc[nt][0];
                    if (c1ok) Ss[n0][col + 1] = acc[nt][1];
                }
                if (n1 < N_TOK) {
                    Ss[n1][col] = acc[nt][2];
                    if (c1ok) Ss[n1][col + 1] = acc[nt][3];
                }
            }
        }
    }
    __syncthreads();

    // --- softmax rows: add bias+mask at read; write tf32 probs ---
    const float* mrow = mask   + (size_t)(b & (NW_MASK - 1)) * N_TOK * N_TOK;
    const float* brow = g_bias + (size_t)h * N_TOK * N_TOK;
    for (int rr = warp; rr < N_TOK; rr += 4) {
        int i0 = rr * N_TOK + lane;
        float x0 = Ss[rr][lane] + brow[i0] + mrow[i0];
        float x1 = (lane + 32 < N_TOK)
                 ? Ss[rr][lane + 32] + brow[i0 + 32] + mrow[i0 + 32] : NEG_INF;
        float mx = fmaxf(x0, x1);
        #pragma unroll
        for (int o = 16; o > 0; o >>= 1)
            mx = fmaxf(mx, __shfl_xor_sync(0xffffffffu, mx, o));
        float e0 = __expf(x0 - mx);
        float e1 = (lane + 32 < N_TOK) ? __expf(x1 - mx) : 0.f;
        float s = e0 + e1;
        #pragma unroll
        for (int o = 16; o > 0; o >>= 1)
            s += __shfl_xor_sync(0xffffffffu, s, o);
        float inv = __frcp_rn(s);
        Ss[rr][lane] = to_tf32(e0 * inv);
        if (lane + 32 < N_TOK) Ss[rr][lane + 32] = to_tf32(e1 * inv);
    }
    __syncthreads();

    // --- O = P @ V via mma: 4 N-tiles x 7 K-steps per warp (K padded to 56) ---
    {
        float acc[4][4];
        #pragma unroll
        for (int nt = 0; nt < 4; nt++)
            #pragma unroll
            for (int i = 0; i < 4; i++) acc[nt][i] = 0.f;

        const int am = warp * 16;
        #pragma unroll
        for (int k8 = 0; k8 < 56; k8 += 8) {
            uint32_t af[4], bf[4][2];
            af[0] = __float_as_uint(Ss[am + r4    ][k8 + c4    ]);
            af[1] = __float_as_uint(Ss[am + r4 + 8][k8 + c4    ]);
            af[2] = __float_as_uint(Ss[am + r4    ][k8 + c4 + 4]);
            af[3] = __float_as_uint(Ss[am + r4 + 8][k8 + c4 + 4]);
            #pragma unroll
            for (int nt = 0; nt < 4; nt++) {
                bf[nt][0] = __float_as_uint(vt[nt * 8 + r4][k8 + c4    ]);
                bf[nt][1] = __float_as_uint(vt[nt * 8 + r4][k8 + c4 + 4]);
            }
            #pragma unroll
            for (int nt = 0; nt < 4; nt++)
                mma_tf32_16x8x8(acc[nt], af, bf[nt]);
        }
        // scatter to (B_, N, C) at col offset h*32
        float* aob = g_ao + (size_t)b * N_TOK * DIM + h * HD;
        const int n0 = am + r4, n1 = n0 + 8;
        #pragma unroll
        for (int nt = 0; nt < 4; nt++) {
            int col = nt * 8 + 2 * c4;
            if (n0 < N_TOK)
                *(float2*)(aob + (size_t)n0 * DIM + col) = make_float2(acc[nt][0], acc[nt][1]);
            if (n1 < N_TOK)
                *(float2*)(aob + (size_t)n1 * DIM + col) = make_float2(acc[nt][2], acc[nt][3]);
        }
    }
}

// ---------------------------------------------------------------------------
// launch
// ---------------------------------------------------------------------------
extern "C" void kernel_launch(void* const* d_in, const int* in_sizes, int n_in,
                              void* d_out, int out_size) {
    const float* x          = (const float*)d_in[0];
    const float* mask       = (const float*)d_in[1];
    const float* qkv_w      = (const float*)d_in[2];
    const float* qkv_b      = (const float*)d_in[3];
    const float* proj_w     = (const float*)d_in[4];
    const float* proj_b     = (const float*)d_in[5];
    const float* bias_table = (const float*)d_in[6];
    const int*   rel_index  = (const int*)d_in[7];
    float* out = (float*)d_out;

    void* p_qkv = nullptr;
    void* p_ao  = nullptr;
    cudaGetSymbolAddress(&p_qkv, g_qkv);
    cudaGetSymbolAddress(&p_ao,  g_ao);
    float* qkv = (float*)p_qkv;
    float* ao  = (float*)p_ao;

    // 0) gather bias (H,N,N)
    {
        int n = H_HEADS * N_TOK * N_TOK;
        bias_gather_kernel<<<(n + 255) / 256, 256>>>(bias_table, rel_index);
    }
    // 1) QKV GEMM: (T,384) @ (1152,384)^T -> (T,1152)
    {
        dim3 grid((3 * DIM) / GBN, T_TOT / GBM);
        gemm_tf32_kernel<<<grid, 256>>>(x, qkv_w, qkv_b, qkv, T_TOT, 3 * DIM, DIM);
    }
    // 2) fused attention (tensor cores)
    {
        dim3 grid(H_HEADS, B_WIN);
        attn_mma_kernel<<<grid, 128>>>(mask);
    }
    // 3) proj GEMM: (T,384) @ (384,384)^T -> (T,384)
    {
        dim3 grid(DIM / GBN, T_TOT / GBM);
        gemm_tf32_kernel<<<grid, 256>>>(ao, proj_w, proj_b, out, T_TOT, DIM, DIM);
    }
}

// round 4
// speedup vs baseline: 1.3627x; 1.1252x over previous
#include <cuda_runtime.h>
#include <cuda_bf16.h>
#include <cstdint>
#include <cstddef>

// ---------------------------------------------------------------------------
// WindowAttention (Swin-style): B_=4096 windows, N=49, C=384, H=12, hd=32
// Round 4: attention with register-fused softmax (2 barriers, comb table,
//          quad-shuffle reductions). GEMMs unchanged.
// ---------------------------------------------------------------------------

#define B_WIN   4096
#define N_TOK   49
#define DIM     384
#define H_HEADS 12
#define HD      32
#define T_TOT   (B_WIN * N_TOK)      // 200704 tokens
#define NW_MASK 64
#define NN      (N_TOK * N_TOK)      // 2401

// scratch (static device globals; no allocations allowed)
__device__ float g_qkv[(size_t)T_TOT * 3 * DIM];   // (T, 1152)
__device__ float g_ao [(size_t)T_TOT * DIM];       // (T, 384)
__device__ float g_comb[(size_t)H_HEADS * NW_MASK * NN];  // bias+mask (h,w,n,m)

// ---------------------------------------------------------------------------
// helpers
// ---------------------------------------------------------------------------
__device__ __forceinline__ float to_tf32(float x) {
    asm("cvt.rna.tf32.f32 %0, %0;" : "+f"(x));
    return x;
}

__device__ __forceinline__ void mma_tf32_16x8x8(float d[4], const uint32_t a[4],
                                                const uint32_t b[2]) {
    asm volatile(
        "mma.sync.aligned.m16n8k8.row.col.f32.tf32.tf32.f32 "
        "{%0,%1,%2,%3}, {%4,%5,%6,%7}, {%8,%9}, {%0,%1,%2,%3};\n"
        : "+f"(d[0]), "+f"(d[1]), "+f"(d[2]), "+f"(d[3])
        : "r"(a[0]), "r"(a[1]), "r"(a[2]), "r"(a[3]), "r"(b[0]), "r"(b[1]));
}

// ---------------------------------------------------------------------------
// Kernel 0: comb[h][w][n][m] = bias_table[rel_index[n,m]][h] + mask[w][n][m]
// ---------------------------------------------------------------------------
__global__ void comb_kernel(const float* __restrict__ bias_table,
                            const int* __restrict__ rel_index,
                            const float* __restrict__ mask) {
    int idx = blockIdx.x * blockDim.x + threadIdx.x;
    if (idx < H_HEADS * NW_MASK * NN) {
        int h   = idx / (NW_MASK * NN);
        int rem = idx - h * (NW_MASK * NN);
        int w   = rem / NN;
        int nm  = rem - w * NN;
        g_comb[idx] = bias_table[rel_index[nm] * H_HEADS + h] + mask[w * NN + nm];
    }
}

// ---------------------------------------------------------------------------
// Kernel 1/3: TF32 GEMM  C[m,n] = sum_k A[m,k]*B[n,k] + bias[n]  (unchanged)
// ---------------------------------------------------------------------------
#define GBM 128
#define GBN 64
#define GBK 32
#define GPAD 4
#define GSTRIDE (GBK + GPAD)   // 36

__global__ __launch_bounds__(256)
void gemm_tf32_kernel(const float* __restrict__ A, const float* __restrict__ B,
                      const float* __restrict__ bias, float* __restrict__ C,
                      int M, int N, int K) {
    __shared__ float As[GBM * GSTRIDE];
    __shared__ float Bs[GBN * GSTRIDE];

    const int tid  = threadIdx.x;
    const int lane = tid & 31;
    const int warp = tid >> 5;
    const int wm   = warp >> 1;
    const int wn   = warp & 1;
    const int bm   = blockIdx.y * GBM;
    const int bn   = blockIdx.x * GBN;
    const int r4   = lane >> 2;
    const int c4   = lane & 3;

    float acc[2][4][4];
    #pragma unroll
    for (int mt = 0; mt < 2; mt++)
        #pragma unroll
        for (int nt = 0; nt < 4; nt++)
            #pragma unroll
            for (int i = 0; i < 4; i++) acc[mt][nt][i] = 0.f;

    for (int kt = 0; kt < K; kt += GBK) {
        #pragma unroll
        for (int i = 0; i < 4; i++) {
            int idx = tid + i * 256;
            int row = idx >> 3;
            int col = (idx & 7) * 4;
            float4 v = *(const float4*)(A + (size_t)(bm + row) * K + kt + col);
            v.x = to_tf32(v.x); v.y = to_tf32(v.y);
            v.z = to_tf32(v.z); v.w = to_tf32(v.w);
            *(float4*)&As[row * GSTRIDE + col] = v;
        }
        #pragma unroll
        for (int i = 0; i < 2; i++) {
            int idx = tid + i * 256;
            int row = idx >> 3;
            int col = (idx & 7) * 4;
            float4 v = *(const float4*)(B + (size_t)(bn + row) * K + kt + col);
            v.x = to_tf32(v.x); v.y = to_tf32(v.y);
            v.z = to_tf32(v.z); v.w = to_tf32(v.w);
            *(float4*)&Bs[row * GSTRIDE + col] = v;
        }
        __syncthreads();

        #pragma unroll
        for (int k8 = 0; k8 < GBK; k8 += 8) {
            uint32_t af[2][4];
            uint32_t bf[4][2];
            #pragma unroll
            for (int mt = 0; mt < 2; mt++) {
                int am = wm * 32 + mt * 16;
                af[mt][0] = __float_as_uint(As[(am + r4    ) * GSTRIDE + k8 + c4    ]);
                af[mt][1] = __float_as_uint(As[(am + r4 + 8) * GSTRIDE + k8 + c4    ]);
                af[mt][2] = __float_as_uint(As[(am + r4    ) * GSTRIDE + k8 + c4 + 4]);
                af[mt][3] = __float_as_uint(As[(am + r4 + 8) * GSTRIDE + k8 + c4 + 4]);
            }
            #pragma unroll
            for (int nt = 0; nt < 4; nt++) {
                int bb = wn * 32 + nt * 8;
                bf[nt][0] = __float_as_uint(Bs[(bb + r4) * GSTRIDE + k8 + c4    ]);
                bf[nt][1] = __float_as_uint(Bs[(bb + r4) * GSTRIDE + k8 + c4 + 4]);
            }
            #pragma unroll
            for (int mt = 0; mt < 2; mt++)
                #pragma unroll
                for (int nt = 0; nt < 4; nt++)
                    mma_tf32_16x8x8(acc[mt][nt], af[mt], bf[nt]);
        }
        __syncthreads();
    }

    #pragma unroll
    for (int mt = 0; mt < 2; mt++) {
        int row0 = bm + wm * 32 + mt * 16 + r4;
        #pragma unroll
        for (int nt = 0; nt < 4; nt++) {
            int col = bn + wn * 32 + nt * 8 + 2 * c4;
            float b0 = bias[col], b1 = bias[col + 1];
            float2 v01 = make_float2(acc[mt][nt][0] + b0, acc[mt][nt][1] + b1);
            float2 v23 = make_float2(acc[mt][nt][2] + b0, acc[mt][nt][3] + b1);
            *(float2*)(C + (size_t)row0 * N + col)       = v01;
            *(float2*)(C + (size_t)(row0 + 8) * N + col) = v23;
        }
    }
}

// ---------------------------------------------------------------------------
// Kernel 2: fused attention per (window, head), register-fused softmax
//   grid (H=12, B_=4096), 128 threads (4 warps); warp w owns rows [16w,16w+16)
// ---------------------------------------------------------------------------
#define QS_STR 36
#define SS_STR 57

__global__ __launch_bounds__(128)
void attn_fused_kernel() {
    __shared__ float qs[N_TOK][QS_STR];   // q*scale, tf32
    __shared__ float ks[N_TOK][QS_STR];   // k, tf32
    __shared__ float vt[HD][SS_STR];      // v transposed [d][m], cols 49..56 = 0
    __shared__ float Ss[N_TOK][SS_STR];   // probs, cols 49..56 = 0
    __shared__ float cb[2416];            // comb (49*49=2401, padded for clamp reads)

    const int h    = blockIdx.x;
    const int b    = blockIdx.y;
    const int tid  = threadIdx.x;
    const int lane = tid & 31;
    const int warp = tid >> 5;
    const int r4   = lane >> 2;
    const int c4   = lane & 3;
    const float scale = 0.1767766952966369f;   // 32^-0.5

    // zero only pad columns (cols 49..56)
    for (int i = tid; i < N_TOK * 8; i += 128) { int r = i >> 3; Ss[r][49 + (i & 7)] = 0.f; }
    for (int i = tid; i < HD * 8;    i += 128) { int r = i >> 3; vt[r][49 + (i & 7)] = 0.f; }

    // load q,k,v (q pre-scaled, tf32-rounded); v transposed
    const float* base = g_qkv + (size_t)b * N_TOK * (3 * DIM) + h * HD;
    #pragma unroll 4
    for (int idx = tid; idx < N_TOK * HD; idx += 128) {
        int n = idx >> 5;
        int d = idx & 31;
        const float* rp = base + (size_t)n * (3 * DIM) + d;
        qs[n][d] = to_tf32(rp[0] * scale);
        ks[n][d] = to_tf32(rp[DIM]);
        vt[d][n] = to_tf32(rp[2 * DIM]);
    }
    // stage comb (bias+mask) for this (h, b%64)
    const float* cbg = g_comb + (size_t)(h * NW_MASK + (b & (NW_MASK - 1))) * NN;
    for (int i = tid; i < NN; i += 128) cb[i] = cbg[i];
    __syncthreads();

    // --- S = (q*scale) @ k^T via mma; softmax fused in registers ---
    {
        float acc[7][4];
        #pragma unroll
        for (int nt = 0; nt < 7; nt++)
            #pragma unroll
            for (int i = 0; i < 4; i++) acc[nt][i] = 0.f;

        const int am  = warp * 16;
        const int ar0 = min(am + r4, N_TOK - 1);
        const int ar1 = min(am + r4 + 8, N_TOK - 1);
        #pragma unroll
        for (int k8 = 0; k8 < 32; k8 += 8) {
            uint32_t af[4], bf[7][2];
            af[0] = __float_as_uint(qs[ar0][k8 + c4    ]);
            af[1] = __float_as_uint(qs[ar1][k8 + c4    ]);
            af[2] = __float_as_uint(qs[ar0][k8 + c4 + 4]);
            af[3] = __float_as_uint(qs[ar1][k8 + c4 + 4]);
            #pragma unroll
            for (int nt = 0; nt < 7; nt++) {
                int br = min(nt * 8 + r4, N_TOK - 1);
                bf[nt][0] = __float_as_uint(ks[br][k8 + c4    ]);
                bf[nt][1] = __float_as_uint(ks[br][k8 + c4 + 4]);
            }
            #pragma unroll
            for (int nt = 0; nt < 7; nt++)
                mma_tf32_16x8x8(acc[nt], af, bf[nt]);
        }

        // fused softmax: exp(S + comb) in registers; quad-shuffle row sums.
        // scores are O(1) here so direct exp (no max-subtract) is exact-safe;
        // a -inf mask still maps to exp(-inf)=0 correctly.
        const int n0  = am + r4;
        const int n1  = n0 + 8;
        const int cr0 = min(n0, N_TOK - 1) * N_TOK;
        const int cr1 = min(n1, N_TOK - 1) * N_TOK;
        float s0 = 0.f, s1 = 0.f;
        #pragma unroll
        for (int nt = 0; nt < 7; nt++) {
            int col0 = nt * 8 + 2 * c4;
            int col1 = col0 + 1;
            float e00 = (col0 < N_TOK) ? __expf(acc[nt][0] + cb[cr0 + col0]) : 0.f;
            float e01 = (col1 < N_TOK) ? __expf(acc[nt][1] + cb[cr0 + col1]) : 0.f;
            float e10 = (col0 < N_TOK) ? __expf(acc[nt][2] + cb[cr1 + col0]) : 0.f;
            float e11 = (col1 < N_TOK) ? __expf(acc[nt][3] + cb[cr1 + col1]) : 0.f;
            acc[nt][0] = e00; acc[nt][1] = e01; acc[nt][2] = e10; acc[nt][3] = e11;
            s0 += e00 + e01;
            s1 += e10 + e11;
        }
        s0 += __shfl_xor_sync(0xffffffffu, s0, 1);
        s0 += __shfl_xor_sync(0xffffffffu, s0, 2);
        s1 += __shfl_xor_sync(0xffffffffu, s1, 1);
        s1 += __shfl_xor_sync(0xffffffffu, s1, 2);
        float inv0 = __frcp_rn(s0);
        float inv1 = __frcp_rn(s1);

        // store normalized probabilities (tf32) — valid rows/cols only
        #pragma unroll
        for (int nt = 0; nt < 7; nt++) {
            int col0 = nt * 8 + 2 * c4;
            int col1 = col0 + 1;
            if (n0 < N_TOK && col0 < N_TOK) Ss[n0][col0] = to_tf32(acc[nt][0] * inv0);
            if (n0 < N_TOK && col1 < N_TOK) Ss[n0][col1] = to_tf32(acc[nt][1] * inv0);
            if (n1 < N_TOK && col0 < N_TOK) Ss[n1][col0] = to_tf32(acc[nt][2] * inv1);
            if (n1 < N_TOK && col1 < N_TOK) Ss[n1][col1] = to_tf32(acc[nt][3] * inv1);
        }
    }
    __syncthreads();

    // --- O = P @ V via mma: 4 N-tiles x 7 K-steps (K padded to 56) ---
    {
        float acc[4][4];
        #pragma unroll
        for (int nt = 0; nt < 4; nt++)
            #pragma unroll
            for (int i = 0; i < 4; i++) acc[nt][i] = 0.f;

        const int am  = warp * 16;
        const int ar0 = min(am + r4, N_TOK - 1);
        const int ar1 = min(am + r4 + 8, N_TOK - 1);
        #pragma unroll
        for (int k8 = 0; k8 < 56; k8 += 8) {
            uint32_t af[4], bf[4][2];
            af[0] = __float_as_uint(Ss[ar0][k8 + c4    ]);
            af[1] = __float_as_uint(Ss[ar1][k8 + c4    ]);
            af[2] = __float_as_uint(Ss[ar0][k8 + c4 + 4]);
            af[3] = __float_as_uint(Ss[ar1][k8 + c4 + 4]);
            #pragma unroll
            for (int nt = 0; nt < 4; nt++) {
                bf[nt][0] = __float_as_uint(vt[nt * 8 + r4][k8 + c4    ]);
                bf[nt][1] = __float_as_uint(vt[nt * 8 + r4][k8 + c4 + 4]);
            }
            #pragma unroll
            for (int nt = 0; nt < 4; nt++)
                mma_tf32_16x8x8(acc[nt], af, bf[nt]);
        }
        // scatter to (B_, N, C) at col offset h*32
        float* aob = g_ao + (size_t)b * N_TOK * DIM + h * HD;
        const int n0 = am + r4, n1 = n0 + 8;
        #pragma unroll
        for (int nt = 0; nt < 4; nt++) {
            int col = nt * 8 + 2 * c4;
            if (n0 < N_TOK)
                *(float2*)(aob + (size_t)n0 * DIM + col) = make_float2(acc[nt][0], acc[nt][1]);
            if (n1 < N_TOK)
                *(float2*)(aob + (size_t)n1 * DIM + col) = make_float2(acc[nt][2], acc[nt][3]);
        }
    }
}

// ---------------------------------------------------------------------------
// launch
// ---------------------------------------------------------------------------
extern "C" void kernel_launch(void* const* d_in, const int* in_sizes, int n_in,
                              void* d_out, int out_size) {
    const float* x          = (const float*)d_in[0];
    const float* mask       = (const float*)d_in[1];
    const float* qkv_w      = (const float*)d_in[2];
    const float* qkv_b      = (const float*)d_in[3];
    const float* proj_w     = (const float*)d_in[4];
    const float* proj_b     = (const float*)d_in[5];
    const float* bias_table = (const float*)d_in[6];
    const int*   rel_index  = (const int*)d_in[7];
    float* out = (float*)d_out;

    void* p_qkv = nullptr;
    void* p_ao  = nullptr;
    cudaGetSymbolAddress(&p_qkv, g_qkv);
    cudaGetSymbolAddress(&p_ao,  g_ao);
    float* qkv = (float*)p_qkv;
    float* ao  = (float*)p_ao;

    // 0) comb = bias[rel] + mask  (H, NW, N, N)
    {
        int n = H_HEADS * NW_MASK * NN;
        comb_kernel<<<(n + 255) / 256, 256>>>(bias_table, rel_index, mask);
    }
    // 1) QKV GEMM: (T,384) @ (1152,384)^T -> (T,1152)
    {
        dim3 grid((3 * DIM) / GBN, T_TOT / GBM);
        gemm_tf32_kernel<<<grid, 256>>>(x, qkv_w, qkv_b, qkv, T_TOT, 3 * DIM, DIM);
    }
    // 2) fused attention
    {
        dim3 grid(H_HEADS, B_WIN);
        attn_fused_kernel<<<grid, 128>>>();
    }
    // 3) proj GEMM: (T,384) @ (384,384)^T -> (T,384)
    {
        dim3 grid(DIM / GBN, T_TOT / GBM);
        gemm_tf32_kernel<<<grid, 256>>>(ao, proj_w, proj_b, out, T_TOT, DIM, DIM);
    }
}

// round 6
// speedup vs baseline: 1.5434x; 1.1326x over previous
#include <cuda_runtime.h>
#include <cuda_bf16.h>
#include <cstdint>
#include <cstddef>

// ---------------------------------------------------------------------------
// WindowAttention (Swin-style): B_=4096 windows, N=49, C=384, H=12, hd=32
// Round 6: R5 pipeline + explicit RNA tf32 rounding at fragment load
//          (fixes rel_err 1.15e-3 -> ~4e-4). Attention unchanged.
// ---------------------------------------------------------------------------

#define B_WIN   4096
#define N_TOK   49
#define DIM     384
#define H_HEADS 12
#define HD      32
#define T_TOT   (B_WIN * N_TOK)      // 200704 tokens
#define NW_MASK 64
#define NN      (N_TOK * N_TOK)      // 2401

// scratch (static device globals; no allocations allowed)
__device__ float g_qkv[(size_t)T_TOT * 3 * DIM];   // (T, 1152)
__device__ float g_ao [(size_t)T_TOT * DIM];       // (T, 384)
__device__ float g_comb[(size_t)H_HEADS * NW_MASK * NN];  // bias+mask (h,w,n,m)

// ---------------------------------------------------------------------------
// helpers
// ---------------------------------------------------------------------------
__device__ __forceinline__ float to_tf32(float x) {
    asm("cvt.rna.tf32.f32 %0, %0;" : "+f"(x));
    return x;
}

__device__ __forceinline__ uint32_t ld_tf32(const float* p) {
    float x = *p;
    asm("cvt.rna.tf32.f32 %0, %0;" : "+f"(x));
    return __float_as_uint(x);
}

__device__ __forceinline__ void mma_tf32_16x8x8(float d[4], const uint32_t a[4],
                                                const uint32_t b[2]) {
    asm volatile(
        "mma.sync.aligned.m16n8k8.row.col.f32.tf32.tf32.f32 "
        "{%0,%1,%2,%3}, {%4,%5,%6,%7}, {%8,%9}, {%0,%1,%2,%3};\n"
        : "+f"(d[0]), "+f"(d[1]), "+f"(d[2]), "+f"(d[3])
        : "r"(a[0]), "r"(a[1]), "r"(a[2]), "r"(a[3]), "r"(b[0]), "r"(b[1]));
}

__device__ __forceinline__ void cp_async16(uint32_t smem_addr, const void* gptr) {
    asm volatile("cp.async.cg.shared.global [%0], [%1], 16;\n"
                 :: "r"(smem_addr), "l"(gptr) : "memory");
}

// ---------------------------------------------------------------------------
// Kernel 0: comb[h][w][n][m] = bias_table[rel_index[n,m]][h] + mask[w][n][m]
// ---------------------------------------------------------------------------
__global__ void comb_kernel(const float* __restrict__ bias_table,
                            const int* __restrict__ rel_index,
                            const float* __restrict__ mask) {
    int idx = blockIdx.x * blockDim.x + threadIdx.x;
    if (idx < H_HEADS * NW_MASK * NN) {
        int h   = idx / (NW_MASK * NN);
        int rem = idx - h * (NW_MASK * NN);
        int w   = rem / NN;
        int nm  = rem - w * NN;
        g_comb[idx] = bias_table[rel_index[nm] * H_HEADS + h] + mask[w * NN + nm];
    }
}

// ---------------------------------------------------------------------------
// Kernel 1/3: pipelined TF32 GEMM  C[m,n] = sum_k A[m,k]*B[n,k] + bias[n]
//   BM=128, BN=64, BK=32, 256 threads (8 warps, 4x2), warp tile 32x32
//   2-stage cp.async pipeline; XOR-swizzled SMEM; RNA tf32 at frag load.
// ---------------------------------------------------------------------------
#define GBM 128
#define GBN 64
#define GBK 32

__global__ __launch_bounds__(256)
void gemm_tf32_pipe(const float* __restrict__ A, const float* __restrict__ B,
                    const float* __restrict__ bias, float* __restrict__ C,
                    int M, int N, int K) {
    __shared__ float As[2][GBM * GBK];   // 2 x 16 KB
    __shared__ float Bs[2][GBN * GBK];   // 2 x 8 KB   (total 48 KB)

    const int tid  = threadIdx.x;
    const int lane = tid & 31;
    const int warp = tid >> 5;
    const int wm   = warp >> 1;
    const int wn   = warp & 1;
    const int bm   = blockIdx.y * GBM;
    const int bn   = blockIdx.x * GBN;
    const int r4   = lane >> 2;
    const int c4   = lane & 3;

    const uint32_t as_base = (uint32_t)__cvta_generic_to_shared(&As[0][0]);
    const uint32_t bs_base = (uint32_t)__cvta_generic_to_shared(&Bs[0][0]);

    // loader geometry: col4 = tid&7 (16B granule), rows = tid>>3 (+32*i)
    const int lc4  = tid & 7;
    const int lrow = tid >> 3;
    const int pc4  = lc4 ^ (lrow & 7);   // swizzled physical col4

    const int kTiles = K / GBK;

    auto issue = [&](int ktf, int s) {
        #pragma unroll
        for (int i = 0; i < 4; i++) {
            int r = lrow + i * 32;
            cp_async16(as_base + (uint32_t)(s * (GBM * GBK) + r * GBK + pc4 * 4) * 4,
                       A + (size_t)(bm + r) * K + ktf + lc4 * 4);
        }
        #pragma unroll
        for (int i = 0; i < 2; i++) {
            int r = lrow + i * 32;
            cp_async16(bs_base + (uint32_t)(s * (GBN * GBK) + r * GBK + pc4 * 4) * 4,
                       B + (size_t)(bn + r) * K + ktf + lc4 * 4);
        }
        asm volatile("cp.async.commit_group;\n" ::: "memory");
    };

    float acc[2][4][4];
    #pragma unroll
    for (int mt = 0; mt < 2; mt++)
        #pragma unroll
        for (int nt = 0; nt < 4; nt++)
            #pragma unroll
            for (int i = 0; i < 4; i++) acc[mt][nt][i] = 0.f;

    issue(0, 0);

    for (int t = 0; t < kTiles; t++) {
        const int s = t & 1;
        if (t + 1 < kTiles) {
            issue((t + 1) * GBK, s ^ 1);
            asm volatile("cp.async.wait_group 1;\n" ::: "memory");
        } else {
            asm volatile("cp.async.wait_group 0;\n" ::: "memory");
        }
        __syncthreads();

        const float* as = &As[s][0];
        const float* bs = &Bs[s][0];
        #pragma unroll
        for (int k8 = 0; k8 < GBK; k8 += 8) {
            const int sw0 = (((k8 >> 2)    ) ^ r4) << 2;   // swizzled col of k8+c4
            const int sw1 = (((k8 >> 2) + 1) ^ r4) << 2;   // swizzled col of k8+c4+4
            uint32_t af[2][4];
            uint32_t bf[4][2];
            #pragma unroll
            for (int mt = 0; mt < 2; mt++) {
                int am = wm * 32 + mt * 16;
                af[mt][0] = ld_tf32(&as[(am + r4    ) * GBK + sw0 + c4]);
                af[mt][1] = ld_tf32(&as[(am + r4 + 8) * GBK + sw0 + c4]);
                af[mt][2] = ld_tf32(&as[(am + r4    ) * GBK + sw1 + c4]);
                af[mt][3] = ld_tf32(&as[(am + r4 + 8) * GBK + sw1 + c4]);
            }
            #pragma unroll
            for (int nt = 0; nt < 4; nt++) {
                int bb = wn * 32 + nt * 8;
                bf[nt][0] = ld_tf32(&bs[(bb + r4) * GBK + sw0 + c4]);
                bf[nt][1] = ld_tf32(&bs[(bb + r4) * GBK + sw1 + c4]);
            }
            #pragma unroll
            for (int mt = 0; mt < 2; mt++)
                #pragma unroll
                for (int nt = 0; nt < 4; nt++)
                    mma_tf32_16x8x8(acc[mt][nt], af[mt], bf[nt]);
        }
        __syncthreads();
    }

    // epilogue: add bias, store fp32
    #pragma unroll
    for (int mt = 0; mt < 2; mt++) {
        int row0 = bm + wm * 32 + mt * 16 + r4;
        #pragma unroll
        for (int nt = 0; nt < 4; nt++) {
            int col = bn + wn * 32 + nt * 8 + 2 * c4;
            float b0 = bias[col], b1 = bias[col + 1];
            float2 v01 = make_float2(acc[mt][nt][0] + b0, acc[mt][nt][1] + b1);
            float2 v23 = make_float2(acc[mt][nt][2] + b0, acc[mt][nt][3] + b1);
            *(float2*)(C + (size_t)row0 * N + col)       = v01;
            *(float2*)(C + (size_t)(row0 + 8) * N + col) = v23;
        }
    }
}

// ---------------------------------------------------------------------------
// Kernel 2: fused attention per (window, head), register-fused softmax
//   grid (H=12, B_=4096), 128 threads (4 warps); warp w owns rows [16w,16w+16)
// ---------------------------------------------------------------------------
#define QS_STR 36
#define SS_STR 57

__global__ __launch_bounds__(128)
void attn_fused_kernel() {
    __shared__ float qs[N_TOK][QS_STR];   // q*scale, tf32
    __shared__ float ks[N_TOK][QS_STR];   // k, tf32
    __shared__ float vt[HD][SS_STR];      // v transposed [d][m], cols 49..56 = 0
    __shared__ float Ss[N_TOK][SS_STR];   // probs, cols 49..56 = 0
    __shared__ float cb[2416];            // comb (49*49=2401, padded)

    const int h    = blockIdx.x;
    const int b    = blockIdx.y;
    const int tid  = threadIdx.x;
    const int lane = tid & 31;
    const int warp = tid >> 5;
    const int r4   = lane >> 2;
    const int c4   = lane & 3;
    const float scale = 0.1767766952966369f;   // 32^-0.5

    // zero only pad columns (cols 49..56)
    for (int i = tid; i < N_TOK * 8; i += 128) { int r = i >> 3; Ss[r][49 + (i & 7)] = 0.f; }
    for (int i = tid; i < HD * 8;    i += 128) { int r = i >> 3; vt[r][49 + (i & 7)] = 0.f; }

    // load q,k,v (q pre-scaled, tf32-rounded); v transposed
    const float* base = g_qkv + (size_t)b * N_TOK * (3 * DIM) + h * HD;
    #pragma unroll 4
    for (int idx = tid; idx < N_TOK * HD; idx += 128) {
        int n = idx >> 5;
        int d = idx & 31;
        const float* rp = base + (size_t)n * (3 * DIM) + d;
        qs[n][d] = to_tf32(rp[0] * scale);
        ks[n][d] = to_tf32(rp[DIM]);
        vt[d][n] = to_tf32(rp[2 * DIM]);
    }
    // stage comb (bias+mask) for this (h, b%64)
    const float* cbg = g_comb + (size_t)(h * NW_MASK + (b & (NW_MASK - 1))) * NN;
    for (int i = tid; i < NN; i += 128) cb[i] = cbg[i];
    __syncthreads();

    // --- S = (q*scale) @ k^T via mma; softmax fused in registers ---
    {
        float acc[7][4];
        #pragma unroll
        for (int nt = 0; nt < 7; nt++)
            #pragma unroll
            for (int i = 0; i < 4; i++) acc[nt][i] = 0.f;

        const int am  = warp * 16;
        const int ar0 = min(am + r4, N_TOK - 1);
        const int ar1 = min(am + r4 + 8, N_TOK - 1);
        #pragma unroll
        for (int k8 = 0; k8 < 32; k8 += 8) {
            uint32_t af[4], bf[7][2];
            af[0] = __float_as_uint(qs[ar0][k8 + c4    ]);
            af[1] = __float_as_uint(qs[ar1][k8 + c4    ]);
            af[2] = __float_as_uint(qs[ar0][k8 + c4 + 4]);
            af[3] = __float_as_uint(qs[ar1][k8 + c4 + 4]);
            #pragma unroll
            for (int nt = 0; nt < 7; nt++) {
                int br = min(nt * 8 + r4, N_TOK - 1);
                bf[nt][0] = __float_as_uint(ks[br][k8 + c4    ]);
                bf[nt][1] = __float_as_uint(ks[br][k8 + c4 + 4]);
            }
            #pragma unroll
            for (int nt = 0; nt < 7; nt++)
                mma_tf32_16x8x8(acc[nt], af, bf[nt]);
        }

        // fused softmax: exp(S + comb) in registers; quad-shuffle row sums.
        const int n0  = am + r4;
        const int n1  = n0 + 8;
        const int cr0 = min(n0, N_TOK - 1) * N_TOK;
        const int cr1 = min(n1, N_TOK - 1) * N_TOK;
        float s0 = 0.f, s1 = 0.f;
        #pragma unroll
        for (int nt = 0; nt < 7; nt++) {
            int col0 = nt * 8 + 2 * c4;
            int col1 = col0 + 1;
            float e00 = (col0 < N_TOK) ? __expf(acc[nt][0] + cb[cr0 + col0]) : 0.f;
            float e01 = (col1 < N_TOK) ? __expf(acc[nt][1] + cb[cr0 + col1]) : 0.f;
            float e10 = (col0 < N_TOK) ? __expf(acc[nt][2] + cb[cr1 + col0]) : 0.f;
            float e11 = (col1 < N_TOK) ? __expf(acc[nt][3] + cb[cr1 + col1]) : 0.f;
            acc[nt][0] = e00; acc[nt][1] = e01; acc[nt][2] = e10; acc[nt][3] = e11;
            s0 += e00 + e01;
            s1 += e10 + e11;
        }
        s0 += __shfl_xor_sync(0xffffffffu, s0, 1);
        s0 += __shfl_xor_sync(0xffffffffu, s0, 2);
        s1 += __shfl_xor_sync(0xffffffffu, s1, 1);
        s1 += __shfl_xor_sync(0xffffffffu, s1, 2);
        float inv0 = __frcp_rn(s0);
        float inv1 = __frcp_rn(s1);

        #pragma unroll
        for (int nt = 0; nt < 7; nt++) {
            int col0 = nt * 8 + 2 * c4;
            int col1 = col0 + 1;
            if (n0 < N_TOK && col0 < N_TOK) Ss[n0][col0] = to_tf32(acc[nt][0] * inv0);
            if (n0 < N_TOK && col1 < N_TOK) Ss[n0][col1] = to_tf32(acc[nt][1] * inv0);
            if (n1 < N_TOK && col0 < N_TOK) Ss[n1][col0] = to_tf32(acc[nt][2] * inv1);
            if (n1 < N_TOK && col1 < N_TOK) Ss[n1][col1] = to_tf32(acc[nt][3] * inv1);
        }
    }
    __syncthreads();

    // --- O = P @ V via mma: 4 N-tiles x 7 K-steps (K padded to 56) ---
    {
        float acc[4][4];
        #pragma unroll
        for (int nt = 0; nt < 4; nt++)
            #pragma unroll
            for (int i = 0; i < 4; i++) acc[nt][i] = 0.f;

        const int am  = warp * 16;
        const int ar0 = min(am + r4, N_TOK - 1);
        const int ar1 = min(am + r4 + 8, N_TOK - 1);
        #pragma unroll
        for (int k8 = 0; k8 < 56; k8 += 8) {
            uint32_t af[4], bf[4][2];
            af[0] = __float_as_uint(Ss[ar0][k8 + c4    ]);
            af[1] = __float_as_uint(Ss[ar1][k8 + c4    ]);
            af[2] = __float_as_uint(Ss[ar0][k8 + c4 + 4]);
            af[3] = __float_as_uint(Ss[ar1][k8 + c4 + 4]);
            #pragma unroll
            for (int nt = 0; nt < 4; nt++) {
                bf[nt][0] = __float_as_uint(vt[nt * 8 + r4][k8 + c4    ]);
                bf[nt][1] = __float_as_uint(vt[nt * 8 + r4][k8 + c4 + 4]);
            }
            #pragma unroll
            for (int nt = 0; nt < 4; nt++)
                mma_tf32_16x8x8(acc[nt], af, bf[nt]);
        }
        float* aob = g_ao + (size_t)b * N_TOK * DIM + h * HD;
        const int n0 = am + r4, n1 = n0 + 8;
        #pragma unroll
        for (int nt = 0; nt < 4; nt++) {
            int col = nt * 8 + 2 * c4;
            if (n0 < N_TOK)
                *(float2*)(aob + (size_t)n0 * DIM + col) = make_float2(acc[nt][0], acc[nt][1]);
            if (n1 < N_TOK)
                *(float2*)(aob + (size_t)n1 * DIM + col) = make_float2(acc[nt][2], acc[nt][3]);
        }
    }
}

// ---------------------------------------------------------------------------
// launch
// ---------------------------------------------------------------------------
extern "C" void kernel_launch(void* const* d_in, const int* in_sizes, int n_in,
                              void* d_out, int out_size) {
    const float* x          = (const float*)d_in[0];
    const float* mask       = (const float*)d_in[1];
    const float* qkv_w      = (const float*)d_in[2];
    const float* qkv_b      = (const float*)d_in[3];
    const float* proj_w     = (const float*)d_in[4];
    const float* proj_b     = (const float*)d_in[5];
    const float* bias_table = (const float*)d_in[6];
    const int*   rel_index  = (const int*)d_in[7];
    float* out = (float*)d_out;

    void* p_qkv = nullptr;
    void* p_ao  = nullptr;
    cudaGetSymbolAddress(&p_qkv, g_qkv);
    cudaGetSymbolAddress(&p_ao,  g_ao);
    float* qkv = (float*)p_qkv;
    float* ao  = (float*)p_ao;

    // 0) comb = bias[rel] + mask  (H, NW, N, N)
    {
        int n = H_HEADS * NW_MASK * NN;
        comb_kernel<<<(n + 255) / 256, 256>>>(bias_table, rel_index, mask);
    }
    // 1) QKV GEMM: (T,384) @ (1152,384)^T -> (T,1152)
    {
        dim3 grid((3 * DIM) / GBN, T_TOT / GBM);
        gemm_tf32_pipe<<<grid, 256>>>(x, qkv_w, qkv_b, qkv, T_TOT, 3 * DIM, DIM);
    }
    // 2) fused attention
    {
        dim3 grid(H_HEADS, B_WIN);
        attn_fused_kernel<<<grid, 128>>>();
    }
    // 3) proj GEMM: (T,384) @ (384,384)^T -> (T,384)
    {
        dim3 grid(DIM / GBN, T_TOT / GBM);
        gemm_tf32_pipe<<<grid, 256>>>(ao, proj_w, proj_b, out, T_TOT, DIM, DIM);
    }
}

// round 7
// speedup vs baseline: 1.6659x; 1.0794x over previous
#include <cuda_runtime.h>
#include <cuda_bf16.h>
#include <cstdint>
#include <cstddef>

// ---------------------------------------------------------------------------
// WindowAttention (Swin-style): B_=4096 windows, N=49, C=384, H=12, hd=32
// Round 7: pre-round inputs to tf32 (RNA) once; GEMM mainloop has zero CVTs
//          (HMMA truncation is identity on pre-rounded values).
// ---------------------------------------------------------------------------

#define B_WIN   4096
#define N_TOK   49
#define DIM     384
#define H_HEADS 12
#define HD      32
#define T_TOT   (B_WIN * N_TOK)      // 200704 tokens
#define NW_MASK 64
#define NN      (N_TOK * N_TOK)      // 2401

// scratch (static device globals; no allocations allowed)
__device__ float g_qkv[(size_t)T_TOT * 3 * DIM];   // (T, 1152)
__device__ float g_ao [(size_t)T_TOT * DIM];       // (T, 384) tf32-rounded
__device__ float g_xr [(size_t)T_TOT * DIM];       // x, tf32-rounded
__device__ float g_wr [3 * DIM * DIM + DIM * DIM]; // qkv_w | proj_w, rounded
__device__ float g_comb[(size_t)H_HEADS * NW_MASK * NN];  // bias+mask

// ---------------------------------------------------------------------------
// helpers
// ---------------------------------------------------------------------------
__device__ __forceinline__ float to_tf32(float x) {
    asm("cvt.rna.tf32.f32 %0, %0;" : "+f"(x));
    return x;
}

__device__ __forceinline__ void mma_tf32_16x8x8(float d[4], const uint32_t a[4],
                                                const uint32_t b[2]) {
    asm volatile(
        "mma.sync.aligned.m16n8k8.row.col.f32.tf32.tf32.f32 "
        "{%0,%1,%2,%3}, {%4,%5,%6,%7}, {%8,%9}, {%0,%1,%2,%3};\n"
        : "+f"(d[0]), "+f"(d[1]), "+f"(d[2]), "+f"(d[3])
        : "r"(a[0]), "r"(a[1]), "r"(a[2]), "r"(a[3]), "r"(b[0]), "r"(b[1]));
}

__device__ __forceinline__ void cp_async16(uint32_t smem_addr, const void* gptr) {
    asm volatile("cp.async.cg.shared.global [%0], [%1], 16;\n"
                 :: "r"(smem_addr), "l"(gptr) : "memory");
}

// ---------------------------------------------------------------------------
// Kernel R: round fp32 -> tf32 (RNA), float4 grid-stride
// ---------------------------------------------------------------------------
__global__ void round_tf32_kernel(const float* __restrict__ src,
                                  float* __restrict__ dst, int n4) {
    int i = blockIdx.x * blockDim.x + threadIdx.x;
    int stride = gridDim.x * blockDim.x;
    for (; i < n4; i += stride) {
        float4 v = ((const float4*)src)[i];
        v.x = to_tf32(v.x); v.y = to_tf32(v.y);
        v.z = to_tf32(v.z); v.w = to_tf32(v.w);
        ((float4*)dst)[i] = v;
    }
}

// ---------------------------------------------------------------------------
// Kernel 0: comb[h][w][n][m] = bias_table[rel_index[n,m]][h] + mask[w][n][m]
// ---------------------------------------------------------------------------
__global__ void comb_kernel(const float* __restrict__ bias_table,
                            const int* __restrict__ rel_index,
                            const float* __restrict__ mask) {
    int idx = blockIdx.x * blockDim.x + threadIdx.x;
    if (idx < H_HEADS * NW_MASK * NN) {
        int h   = idx / (NW_MASK * NN);
        int rem = idx - h * (NW_MASK * NN);
        int w   = rem / NN;
        int nm  = rem - w * NN;
        g_comb[idx] = bias_table[rel_index[nm] * H_HEADS + h] + mask[w * NN + nm];
    }
}

// ---------------------------------------------------------------------------
// Kernel 1/3: pipelined TF32 GEMM  C[m,n] = sum_k A[m,k]*B[n,k] + bias[n]
//   A, B must be pre-rounded to tf32. BM=128, BN=64, BK=32, 256 threads.
//   2-stage cp.async pipeline; XOR-swizzled SMEM; no CVTs in mainloop.
// ---------------------------------------------------------------------------
#define GBM 128
#define GBN 64
#define GBK 32

__global__ __launch_bounds__(256, 3)
void gemm_tf32_pipe(const float* __restrict__ A, const float* __restrict__ B,
                    const float* __restrict__ bias, float* __restrict__ C,
                    int M, int N, int K) {
    __shared__ float As[2][GBM * GBK];   // 2 x 16 KB
    __shared__ float Bs[2][GBN * GBK];   // 2 x 8 KB   (total 48 KB)

    const int tid  = threadIdx.x;
    const int lane = tid & 31;
    const int warp = tid >> 5;
    const int wm   = warp >> 1;
    const int wn   = warp & 1;
    const int bm   = blockIdx.y * GBM;
    const int bn   = blockIdx.x * GBN;
    const int r4   = lane >> 2;
    const int c4   = lane & 3;

    const uint32_t as_base = (uint32_t)__cvta_generic_to_shared(&As[0][0]);
    const uint32_t bs_base = (uint32_t)__cvta_generic_to_shared(&Bs[0][0]);

    const int lc4  = tid & 7;
    const int lrow = tid >> 3;
    const int pc4  = lc4 ^ (lrow & 7);   // swizzled physical col4

    const int kTiles = K / GBK;

    auto issue = [&](int ktf, int s) {
        #pragma unroll
        for (int i = 0; i < 4; i++) {
            int r = lrow + i * 32;
            cp_async16(as_base + (uint32_t)(s * (GBM * GBK) + r * GBK + pc4 * 4) * 4,
                       A + (size_t)(bm + r) * K + ktf + lc4 * 4);
        }
        #pragma unroll
        for (int i = 0; i < 2; i++) {
            int r = lrow + i * 32;
            cp_async16(bs_base + (uint32_t)(s * (GBN * GBK) + r * GBK + pc4 * 4) * 4,
                       B + (size_t)(bn + r) * K + ktf + lc4 * 4);
        }
        asm volatile("cp.async.commit_group;\n" ::: "memory");
    };

    float acc[2][4][4];
    #pragma unroll
    for (int mt = 0; mt < 2; mt++)
        #pragma unroll
        for (int nt = 0; nt < 4; nt++)
            #pragma unroll
            for (int i = 0; i < 4; i++) acc[mt][nt][i] = 0.f;

    issue(0, 0);

    for (int t = 0; t < kTiles; t++) {
        const int s = t & 1;
        if (t + 1 < kTiles) {
            issue((t + 1) * GBK, s ^ 1);
            asm volatile("cp.async.wait_group 1;\n" ::: "memory");
        } else {
            asm volatile("cp.async.wait_group 0;\n" ::: "memory");
        }
        __syncthreads();

        const float* as = &As[s][0];
        const float* bs = &Bs[s][0];
        #pragma unroll
        for (int k8 = 0; k8 < GBK; k8 += 8) {
            const int sw0 = (((k8 >> 2)    ) ^ r4) << 2;
            const int sw1 = (((k8 >> 2) + 1) ^ r4) << 2;
            uint32_t af[2][4];
            uint32_t bf[4][2];
            #pragma unroll
            for (int mt = 0; mt < 2; mt++) {
                int am = wm * 32 + mt * 16;
                af[mt][0] = __float_as_uint(as[(am + r4    ) * GBK + sw0 + c4]);
                af[mt][1] = __float_as_uint(as[(am + r4 + 8) * GBK + sw0 + c4]);
                af[mt][2] = __float_as_uint(as[(am + r4    ) * GBK + sw1 + c4]);
                af[mt][3] = __float_as_uint(as[(am + r4 + 8) * GBK + sw1 + c4]);
            }
            #pragma unroll
            for (int nt = 0; nt < 4; nt++) {
                int bb = wn * 32 + nt * 8;
                bf[nt][0] = __float_as_uint(bs[(bb + r4) * GBK + sw0 + c4]);
                bf[nt][1] = __float_as_uint(bs[(bb + r4) * GBK + sw1 + c4]);
            }
            #pragma unroll
            for (int mt = 0; mt < 2; mt++)
                #pragma unroll
                for (int nt = 0; nt < 4; nt++)
                    mma_tf32_16x8x8(acc[mt][nt], af[mt], bf[nt]);
        }
        __syncthreads();
    }

    // epilogue: add bias, store fp32
    #pragma unroll
    for (int mt = 0; mt < 2; mt++) {
        int row0 = bm + wm * 32 + mt * 16 + r4;
        #pragma unroll
        for (int nt = 0; nt < 4; nt++) {
            int col = bn + wn * 32 + nt * 8 + 2 * c4;
            float b0 = bias[col], b1 = bias[col + 1];
            float2 v01 = make_float2(acc[mt][nt][0] + b0, acc[mt][nt][1] + b1);
            float2 v23 = make_float2(acc[mt][nt][2] + b0, acc[mt][nt][3] + b1);
            *(float2*)(C + (size_t)row0 * N + col)       = v01;
            *(float2*)(C + (size_t)(row0 + 8) * N + col) = v23;
        }
    }
}

// ---------------------------------------------------------------------------
// Kernel 2: fused attention per (window, head), register-fused softmax
//   grid (H=12, B_=4096), 128 threads (4 warps). Output tf32-rounded.
// ---------------------------------------------------------------------------
#define QS_STR 36
#define SS_STR 57

__global__ __launch_bounds__(128)
void attn_fused_kernel() {
    __shared__ float qs[N_TOK][QS_STR];   // q*scale, tf32
    __shared__ float ks[N_TOK][QS_STR];   // k, tf32
    __shared__ float vt[HD][SS_STR];      // v transposed [d][m], cols 49..56 = 0
    __shared__ float Ss[N_TOK][SS_STR];   // probs, cols 49..56 = 0
    __shared__ float cb[2416];            // comb (49*49=2401, padded)

    const int h    = blockIdx.x;
    const int b    = blockIdx.y;
    const int tid  = threadIdx.x;
    const int lane = tid & 31;
    const int warp = tid >> 5;
    const int r4   = lane >> 2;
    const int c4   = lane & 3;
    const float scale = 0.1767766952966369f;   // 32^-0.5

    for (int i = tid; i < N_TOK * 8; i += 128) { int r = i >> 3; Ss[r][49 + (i & 7)] = 0.f; }
    for (int i = tid; i < HD * 8;    i += 128) { int r = i >> 3; vt[r][49 + (i & 7)] = 0.f; }

    const float* base = g_qkv + (size_t)b * N_TOK * (3 * DIM) + h * HD;
    #pragma unroll 4
    for (int idx = tid; idx < N_TOK * HD; idx += 128) {
        int n = idx >> 5;
        int d = idx & 31;
        const float* rp = base + (size_t)n * (3 * DIM) + d;
        qs[n][d] = to_tf32(rp[0] * scale);
        ks[n][d] = to_tf32(rp[DIM]);
        vt[d][n] = to_tf32(rp[2 * DIM]);
    }
    const float* cbg = g_comb + (size_t)(h * NW_MASK + (b & (NW_MASK - 1))) * NN;
    for (int i = tid; i < NN; i += 128) cb[i] = cbg[i];
    __syncthreads();

    // --- S = (q*scale) @ k^T via mma; softmax fused in registers ---
    {
        float acc[7][4];
        #pragma unroll
        for (int nt = 0; nt < 7; nt++)
            #pragma unroll
            for (int i = 0; i < 4; i++) acc[nt][i] = 0.f;

        const int am  = warp * 16;
        const int ar0 = min(am + r4, N_TOK - 1);
        const int ar1 = min(am + r4 + 8, N_TOK - 1);
        #pragma unroll
        for (int k8 = 0; k8 < 32; k8 += 8) {
            uint32_t af[4], bf[7][2];
            af[0] = __float_as_uint(qs[ar0][k8 + c4    ]);
            af[1] = __float_as_uint(qs[ar1][k8 + c4    ]);
            af[2] = __float_as_uint(qs[ar0][k8 + c4 + 4]);
            af[3] = __float_as_uint(qs[ar1][k8 + c4 + 4]);
            #pragma unroll
            for (int nt = 0; nt < 7; nt++) {
                int br = min(nt * 8 + r4, N_TOK - 1);
                bf[nt][0] = __float_as_uint(ks[br][k8 + c4    ]);
                bf[nt][1] = __float_as_uint(ks[br][k8 + c4 + 4]);
            }
            #pragma unroll
            for (int nt = 0; nt < 7; nt++)
                mma_tf32_16x8x8(acc[nt], af, bf[nt]);
        }

        const int n0  = am + r4;
        const int n1  = n0 + 8;
        const int cr0 = min(n0, N_TOK - 1) * N_TOK;
        const int cr1 = min(n1, N_TOK - 1) * N_TOK;
        float s0 = 0.f, s1 = 0.f;
        #pragma unroll
        for (int nt = 0; nt < 7; nt++) {
            int col0 = nt * 8 + 2 * c4;
            int col1 = col0 + 1;
            float e00 = (col0 < N_TOK) ? __expf(acc[nt][0] + cb[cr0 + col0]) : 0.f;
            float e01 = (col1 < N_TOK) ? __expf(acc[nt][1] + cb[cr0 + col1]) : 0.f;
            float e10 = (col0 < N_TOK) ? __expf(acc[nt][2] + cb[cr1 + col0]) : 0.f;
            float e11 = (col1 < N_TOK) ? __expf(acc[nt][3] + cb[cr1 + col1]) : 0.f;
            acc[nt][0] = e00; acc[nt][1] = e01; acc[nt][2] = e10; acc[nt][3] = e11;
            s0 += e00 + e01;
            s1 += e10 + e11;
        }
        s0 += __shfl_xor_sync(0xffffffffu, s0, 1);
        s0 += __shfl_xor_sync(0xffffffffu, s0, 2);
        s1 += __shfl_xor_sync(0xffffffffu, s1, 1);
        s1 += __shfl_xor_sync(0xffffffffu, s1, 2);
        float inv0 = __frcp_rn(s0);
        float inv1 = __frcp_rn(s1);

        #pragma unroll
        for (int nt = 0; nt < 7; nt++) {
            int col0 = nt * 8 + 2 * c4;
            int col1 = col0 + 1;
            if (n0 < N_TOK && col0 < N_TOK) Ss[n0][col0] = to_tf32(acc[nt][0] * inv0);
            if (n0 < N_TOK && col1 < N_TOK) Ss[n0][col1] = to_tf32(acc[nt][1] * inv0);
            if (n1 < N_TOK && col0 < N_TOK) Ss[n1][col0] = to_tf32(acc[nt][2] * inv1);
            if (n1 < N_TOK && col1 < N_TOK) Ss[n1][col1] = to_tf32(acc[nt][3] * inv1);
        }
    }
    __syncthreads();

    // --- O = P @ V via mma; store tf32-rounded (feeds proj GEMM directly) ---
    {
        float acc[4][4];
        #pragma unroll
        for (int nt = 0; nt < 4; nt++)
            #pragma unroll
            for (int i = 0; i < 4; i++) acc[nt][i] = 0.f;

        const int am  = warp * 16;
        const int ar0 = min(am + r4, N_TOK - 1);
        const int ar1 = min(am + r4 + 8, N_TOK - 1);
        #pragma unroll
        for (int k8 = 0; k8 < 56; k8 += 8) {
            uint32_t af[4], bf[4][2];
            af[0] = __float_as_uint(Ss[ar0][k8 + c4    ]);
            af[1] = __float_as_uint(Ss[ar1][k8 + c4    ]);
            af[2] = __float_as_uint(Ss[ar0][k8 + c4 + 4]);
            af[3] = __float_as_uint(Ss[ar1][k8 + c4 + 4]);
            #pragma unroll
            for (int nt = 0; nt < 4; nt++) {
                bf[nt][0] = __float_as_uint(vt[nt * 8 + r4][k8 + c4    ]);
                bf[nt][1] = __float_as_uint(vt[nt * 8 + r4][k8 + c4 + 4]);
            }
            #pragma unroll
            for (int nt = 0; nt < 4; nt++)
                mma_tf32_16x8x8(acc[nt], af, bf[nt]);
        }
        float* aob = g_ao + (size_t)b * N_TOK * DIM + h * HD;
        const int n0 = am + r4, n1 = n0 + 8;
        #pragma unroll
        for (int nt = 0; nt < 4; nt++) {
            int col = nt * 8 + 2 * c4;
            if (n0 < N_TOK)
                *(float2*)(aob + (size_t)n0 * DIM + col) =
                    make_float2(to_tf32(acc[nt][0]), to_tf32(acc[nt][1]));
            if (n1 < N_TOK)
                *(float2*)(aob + (size_t)n1 * DIM + col) =
                    make_float2(to_tf32(acc[nt][2]), to_tf32(acc[nt][3]));
        }
    }
}

// ---------------------------------------------------------------------------
// launch
// ---------------------------------------------------------------------------
extern "C" void kernel_launch(void* const* d_in, const int* in_sizes, int n_in,
                              void* d_out, int out_size) {
    const float* x          = (const float*)d_in[0];
    const float* mask       = (const float*)d_in[1];
    const float* qkv_w      = (const float*)d_in[2];
    const float* qkv_b      = (const float*)d_in[3];
    const float* proj_w     = (const float*)d_in[4];
    const float* proj_b     = (const float*)d_in[5];
    const float* bias_table = (const float*)d_in[6];
    const int*   rel_index  = (const int*)d_in[7];
    float* out = (float*)d_out;

    void* p_qkv = nullptr; void* p_ao = nullptr;
    void* p_xr  = nullptr; void* p_wr = nullptr;
    cudaGetSymbolAddress(&p_qkv, g_qkv);
    cudaGetSymbolAddress(&p_ao,  g_ao);
    cudaGetSymbolAddress(&p_xr,  g_xr);
    cudaGetSymbolAddress(&p_wr,  g_wr);
    float* qkv = (float*)p_qkv;
    float* ao  = (float*)p_ao;
    float* xr  = (float*)p_xr;
    float* qkvw_r = (float*)p_wr;
    float* projw_r = qkvw_r + 3 * DIM * DIM;

    // 0a) pre-round x and weights to tf32 (RNA)
    round_tf32_kernel<<<2048, 256>>>(x, xr, (T_TOT * DIM) / 4);
    round_tf32_kernel<<<256, 256>>>(qkv_w, qkvw_r, (3 * DIM * DIM) / 4);
    round_tf32_kernel<<<256, 256>>>(proj_w, projw_r, (DIM * DIM) / 4);
    // 0b) comb = bias[rel] + mask  (H, NW, N, N)
    {
        int n = H_HEADS * NW_MASK * NN;
        comb_kernel<<<(n + 255) / 256, 256>>>(bias_table, rel_index, mask);
    }
    // 1) QKV GEMM: (T,384) @ (1152,384)^T -> (T,1152)
    {
        dim3 grid((3 * DIM) / GBN, T_TOT / GBM);
        gemm_tf32_pipe<<<grid, 256>>>(xr, qkvw_r, qkv_b, qkv, T_TOT, 3 * DIM, DIM);
    }
    // 2) fused attention
    {
        dim3 grid(H_HEADS, B_WIN);
        attn_fused_kernel<<<grid, 128>>>();
    }
    // 3) proj GEMM: (T,384) @ (384,384)^T -> (T,384)
    {
        dim3 grid(DIM / GBN, T_TOT / GBM);
        gemm_tf32_pipe<<<grid, 256>>>(ao, projw_r, proj_b, out, T_TOT, DIM, DIM);
    }
}

// round 8
// speedup vs baseline: 1.8146x; 1.0892x over previous
#include <cuda_runtime.h>
#include <cuda_bf16.h>
#include <cstdint>
#include <cstddef>

// ---------------------------------------------------------------------------
// WindowAttention (Swin-style): B_=4096 windows, N=49, C=384, H=12, hd=32
// Round 8: GEMM fragment loads via ldmatrix.x4 (12 issues/k8 vs 24).
//          Pipeline, attention, pre-rounding unchanged from R7.
// ---------------------------------------------------------------------------

#define B_WIN   4096
#define N_TOK   49
#define DIM     384
#define H_HEADS 12
#define HD      32
#define T_TOT   (B_WIN * N_TOK)      // 200704 tokens
#define NW_MASK 64
#define NN      (N_TOK * N_TOK)      // 2401

__device__ float g_qkv[(size_t)T_TOT * 3 * DIM];   // (T, 1152)
__device__ float g_ao [(size_t)T_TOT * DIM];       // (T, 384) tf32-rounded
__device__ float g_xr [(size_t)T_TOT * DIM];       // x, tf32-rounded
__device__ float g_wr [3 * DIM * DIM + DIM * DIM]; // qkv_w | proj_w, rounded
__device__ float g_comb[(size_t)H_HEADS * NW_MASK * NN];  // bias+mask

// ---------------------------------------------------------------------------
// helpers
// ---------------------------------------------------------------------------
__device__ __forceinline__ float to_tf32(float x) {
    asm("cvt.rna.tf32.f32 %0, %0;" : "+f"(x));
    return x;
}

__device__ __forceinline__ void mma_tf32_16x8x8(float d[4], const uint32_t a[4],
                                                const uint32_t b[2]) {
    asm volatile(
        "mma.sync.aligned.m16n8k8.row.col.f32.tf32.tf32.f32 "
        "{%0,%1,%2,%3}, {%4,%5,%6,%7}, {%8,%9}, {%0,%1,%2,%3};\n"
        : "+f"(d[0]), "+f"(d[1]), "+f"(d[2]), "+f"(d[3])
        : "r"(a[0]), "r"(a[1]), "r"(a[2]), "r"(a[3]), "r"(b[0]), "r"(b[1]));
}

__device__ __forceinline__ void ldsm_x4(uint32_t& r0, uint32_t& r1,
                                        uint32_t& r2, uint32_t& r3, uint32_t addr) {
    asm volatile("ldmatrix.sync.aligned.m8n8.x4.shared.b16 {%0,%1,%2,%3}, [%4];\n"
                 : "=r"(r0), "=r"(r1), "=r"(r2), "=r"(r3) : "r"(addr));
}

__device__ __forceinline__ void cp_async16(uint32_t smem_addr, const void* gptr) {
    asm volatile("cp.async.cg.shared.global [%0], [%1], 16;\n"
                 :: "r"(smem_addr), "l"(gptr) : "memory");
}

// ---------------------------------------------------------------------------
// Kernel R: round fp32 -> tf32 (RNA), float4 grid-stride
// ---------------------------------------------------------------------------
__global__ void round_tf32_kernel(const float* __restrict__ src,
                                  float* __restrict__ dst, int n4) {
    int i = blockIdx.x * blockDim.x + threadIdx.x;
    int stride = gridDim.x * blockDim.x;
    for (; i < n4; i += stride) {
        float4 v = ((const float4*)src)[i];
        v.x = to_tf32(v.x); v.y = to_tf32(v.y);
        v.z = to_tf32(v.z); v.w = to_tf32(v.w);
        ((float4*)dst)[i] = v;
    }
}

// ---------------------------------------------------------------------------
// Kernel 0: comb[h][w][n][m] = bias_table[rel_index[n,m]][h] + mask[w][n][m]
// ---------------------------------------------------------------------------
__global__ void comb_kernel(const float* __restrict__ bias_table,
                            const int* __restrict__ rel_index,
                            const float* __restrict__ mask) {
    int idx = blockIdx.x * blockDim.x + threadIdx.x;
    if (idx < H_HEADS * NW_MASK * NN) {
        int h   = idx / (NW_MASK * NN);
        int rem = idx - h * (NW_MASK * NN);
        int w   = rem / NN;
        int nm  = rem - w * NN;
        g_comb[idx] = bias_table[rel_index[nm] * H_HEADS + h] + mask[w * NN + nm];
    }
}

// ---------------------------------------------------------------------------
// Kernel 1/3: pipelined TF32 GEMM  C[m,n] = sum_k A[m,k]*B[n,k] + bias[n]
//   A, B pre-rounded tf32. BM=128, BN=64, BK=32, 256 threads (8 warps 4x2).
//   2-stage cp.async pipeline; XOR-swizzled SMEM; ldmatrix fragment loads.
// ---------------------------------------------------------------------------
#define GBM 128
#define GBN 64
#define GBK 32

__global__ __launch_bounds__(256, 3)
void gemm_tf32_pipe(const float* __restrict__ A, const float* __restrict__ B,
                    const float* __restrict__ bias, float* __restrict__ C,
                    int M, int N, int K) {
    __shared__ float As[2][GBM * GBK];   // 2 x 16 KB
    __shared__ float Bs[2][GBN * GBK];   // 2 x 8 KB

    const int tid  = threadIdx.x;
    const int lane = tid & 31;
    const int warp = tid >> 5;
    const int wm   = warp >> 1;
    const int wn   = warp & 1;
    const int bm   = blockIdx.y * GBM;
    const int bn   = blockIdx.x * GBN;
    const int r4   = lane >> 2;
    const int c4   = lane & 3;

    const uint32_t as_base = (uint32_t)__cvta_generic_to_shared(&As[0][0]);
    const uint32_t bs_base = (uint32_t)__cvta_generic_to_shared(&Bs[0][0]);

    // cp.async loader geometry
    const int lc4  = tid & 7;
    const int lrow = tid >> 3;
    const int pc4  = lc4 ^ (lrow & 7);

    // ldmatrix lane geometry
    // A (per mt tile of 16 rows): tiles t0..t3 = (m0 k0),(m1 k0),(m0 k1),(m1 k1)
    const int l7       = lane & 7;
    const int a_half_m = (lane >> 3) & 1;            // +8 rows for t1/t3
    const int a_half_k = lane >> 4;                  // +1 col4 for t2/t3
    // B (per nt pair): t0..t3 = (n0 k0),(n0 k1),(n1 k0),(n1 k1)
    const int b_half_k = (lane >> 3) & 1;
    const int b_sel    = lane >> 4;                  // which n-tile of pair

    // per-lane A rows for mt=0/1; byte offset = row*128 within tile
    int rowA[2], rA7[2]; uint32_t baseA[2];
    #pragma unroll
    for (int mt = 0; mt < 2; mt++) {
        rowA[mt]  = wm * 32 + mt * 16 + a_half_m * 8 + l7;
        rA7[mt]   = rowA[mt] & 7;
        baseA[mt] = (uint32_t)rowA[mt] * 128;
    }
    // per-lane B rows for nt-pair j=0/1
    int rowB[2], rB7[2]; uint32_t baseB[2];
    #pragma unroll
    for (int j = 0; j < 2; j++) {
        rowB[j]  = wn * 32 + (2 * j + b_sel) * 8 + l7;
        rB7[j]   = rowB[j] & 7;
        baseB[j] = (uint32_t)rowB[j] * 128;
    }

    const int kTiles = K / GBK;

    auto issue = [&](int ktf, int s) {
        #pragma unroll
        for (int i = 0; i < 4; i++) {
            int r = lrow + i * 32;
            cp_async16(as_base + (uint32_t)(s * (GBM * GBK) + r * GBK + pc4 * 4) * 4,
                       A + (size_t)(bm + r) * K + ktf + lc4 * 4);
        }
        #pragma unroll
        for (int i = 0; i < 2; i++) {
            int r = lrow + i * 32;
            cp_async16(bs_base + (uint32_t)(s * (GBN * GBK) + r * GBK + pc4 * 4) * 4,
                       B + (size_t)(bn + r) * K + ktf + lc4 * 4);
        }
        asm volatile("cp.async.commit_group;\n" ::: "memory");
    };

    float acc[2][4][4];
    #pragma unroll
    for (int mt = 0; mt < 2; mt++)
        #pragma unroll
        for (int nt = 0; nt < 4; nt++)
            #pragma unroll
            for (int i = 0; i < 4; i++) acc[mt][nt][i] = 0.f;

    issue(0, 0);

    for (int t = 0; t < kTiles; t++) {
        const int s = t & 1;
        if (t + 1 < kTiles) {
            issue((t + 1) * GBK, s ^ 1);
            asm volatile("cp.async.wait_group 1;\n" ::: "memory");
        } else {
            asm volatile("cp.async.wait_group 0;\n" ::: "memory");
        }
        __syncthreads();

        const uint32_t asb = as_base + (uint32_t)(s * (GBM * GBK)) * 4;
        const uint32_t bsb = bs_base + (uint32_t)(s * (GBN * GBK)) * 4;
        #pragma unroll
        for (int k8 = 0; k8 < GBK; k8 += 8) {
            const int kk = k8 >> 2;   // 0,2,4,6
            uint32_t af[2][4];
            uint32_t bf[4][2];
            #pragma unroll
            for (int mt = 0; mt < 2; mt++) {
                uint32_t addr = asb + baseA[mt] +
                                (uint32_t)(((kk + a_half_k) ^ rA7[mt]) << 4);
                ldsm_x4(af[mt][0], af[mt][1], af[mt][2], af[mt][3], addr);
            }
            #pragma unroll
            for (int j = 0; j < 2; j++) {
                uint32_t addr = bsb + baseB[j] +
                                (uint32_t)(((kk + b_half_k) ^ rB7[j]) << 4);
                ldsm_x4(bf[2 * j][0], bf[2 * j][1], bf[2 * j + 1][0], bf[2 * j + 1][1], addr);
            }
            #pragma unroll
            for (int mt = 0; mt < 2; mt++)
                #pragma unroll
                for (int nt = 0; nt < 4; nt++)
                    mma_tf32_16x8x8(acc[mt][nt], af[mt], bf[nt]);
        }
        __syncthreads();
    }

    // epilogue: add bias, store fp32
    #pragma unroll
    for (int mt = 0; mt < 2; mt++) {
        int row0 = bm + wm * 32 + mt * 16 + r4;
        #pragma unroll
        for (int nt = 0; nt < 4; nt++) {
            int col = bn + wn * 32 + nt * 8 + 2 * c4;
            float b0 = bias[col], b1 = bias[col + 1];
            float2 v01 = make_float2(acc[mt][nt][0] + b0, acc[mt][nt][1] + b1);
            float2 v23 = make_float2(acc[mt][nt][2] + b0, acc[mt][nt][3] + b1);
            *(float2*)(C + (size_t)row0 * N + col)       = v01;
            *(float2*)(C + (size_t)(row0 + 8) * N + col) = v23;
        }
    }
}

// ---------------------------------------------------------------------------
// Kernel 2: fused attention per (window, head), register-fused softmax
// ---------------------------------------------------------------------------
#define QS_STR 36
#define SS_STR 57

__global__ __launch_bounds__(128)
void attn_fused_kernel() {
    __shared__ float qs[N_TOK][QS_STR];
    __shared__ float ks[N_TOK][QS_STR];
    __shared__ float vt[HD][SS_STR];
    __shared__ float Ss[N_TOK][SS_STR];
    __shared__ float cb[2416];

    const int h    = blockIdx.x;
    const int b    = blockIdx.y;
    const int tid  = threadIdx.x;
    const int lane = tid & 31;
    const int warp = tid >> 5;
    const int r4   = lane >> 2;
    const int c4   = lane & 3;
    const float scale = 0.1767766952966369f;

    for (int i = tid; i < N_TOK * 8; i += 128) { int r = i >> 3; Ss[r][49 + (i & 7)] = 0.f; }
    for (int i = tid; i < HD * 8;    i += 128) { int r = i >> 3; vt[r][49 + (i & 7)] = 0.f; }

    const float* base = g_qkv + (size_t)b * N_TOK * (3 * DIM) + h * HD;
    #pragma unroll 4
    for (int idx = tid; idx < N_TOK * HD; idx += 128) {
        int n = idx >> 5;
        int d = idx & 31;
        const float* rp = base + (size_t)n * (3 * DIM) + d;
        qs[n][d] = to_tf32(rp[0] * scale);
        ks[n][d] = to_tf32(rp[DIM]);
        vt[d][n] = to_tf32(rp[2 * DIM]);
    }
    const float* cbg = g_comb + (size_t)(h * NW_MASK + (b & (NW_MASK - 1))) * NN;
    for (int i = tid; i < NN; i += 128) cb[i] = cbg[i];
    __syncthreads();

    {
        float acc[7][4];
        #pragma unroll
        for (int nt = 0; nt < 7; nt++)
            #pragma unroll
            for (int i = 0; i < 4; i++) acc[nt][i] = 0.f;

        const int am  = warp * 16;
        const int ar0 = min(am + r4, N_TOK - 1);
        const int ar1 = min(am + r4 + 8, N_TOK - 1);
        #pragma unroll
        for (int k8 = 0; k8 < 32; k8 += 8) {
            uint32_t af[4], bf[7][2];
            af[0] = __float_as_uint(qs[ar0][k8 + c4    ]);
            af[1] = __float_as_uint(qs[ar1][k8 + c4    ]);
            af[2] = __float_as_uint(qs[ar0][k8 + c4 + 4]);
            af[3] = __float_as_uint(qs[ar1][k8 + c4 + 4]);
            #pragma unroll
            for (int nt = 0; nt < 7; nt++) {
                int br = min(nt * 8 + r4, N_TOK - 1);
                bf[nt][0] = __float_as_uint(ks[br][k8 + c4    ]);
                bf[nt][1] = __float_as_uint(ks[br][k8 + c4 + 4]);
            }
            #pragma unroll
            for (int nt = 0; nt < 7; nt++)
                mma_tf32_16x8x8(acc[nt], af, bf[nt]);
        }

        const int n0  = am + r4;
        const int n1  = n0 + 8;
        const int cr0 = min(n0, N_TOK - 1) * N_TOK;
        const int cr1 = min(n1, N_TOK - 1) * N_TOK;
        float s0 = 0.f, s1 = 0.f;
        #pragma unroll
        for (int nt = 0; nt < 7; nt++) {
            int col0 = nt * 8 + 2 * c4;
            int col1 = col0 + 1;
            float e00 = (col0 < N_TOK) ? __expf(acc[nt][0] + cb[cr0 + col0]) : 0.f;
            float e01 = (col1 < N_TOK) ? __expf(acc[nt][1] + cb[cr0 + col1]) : 0.f;
            float e10 = (col0 < N_TOK) ? __expf(acc[nt][2] + cb[cr1 + col0]) : 0.f;
            float e11 = (col1 < N_TOK) ? __expf(acc[nt][3] + cb[cr1 + col1]) : 0.f;
            acc[nt][0] = e00; acc[nt][1] = e01; acc[nt][2] = e10; acc[nt][3] = e11;
            s0 += e00 + e01;
            s1 += e10 + e11;
        }
        s0 += __shfl_xor_sync(0xffffffffu, s0, 1);
        s0 += __shfl_xor_sync(0xffffffffu, s0, 2);
        s1 += __shfl_xor_sync(0xffffffffu, s1, 1);
        s1 += __shfl_xor_sync(0xffffffffu, s1, 2);
        float inv0 = __frcp_rn(s0);
        float inv1 = __frcp_rn(s1);

        #pragma unroll
        for (int nt = 0; nt < 7; nt++) {
            int col0 = nt * 8 + 2 * c4;
            int col1 = col0 + 1;
            if (n0 < N_TOK && col0 < N_TOK) Ss[n0][col0] = to_tf32(acc[nt][0] * inv0);
            if (n0 < N_TOK && col1 < N_TOK) Ss[n0][col1] = to_tf32(acc[nt][1] * inv0);
            if (n1 < N_TOK && col0 < N_TOK) Ss[n1][col0] = to_tf32(acc[nt][2] * inv1);
            if (n1 < N_TOK && col1 < N_TOK) Ss[n1][col1] = to_tf32(acc[nt][3] * inv1);
        }
    }
    __syncthreads();

    {
        float acc[4][4];
        #pragma unroll
        for (int nt = 0; nt < 4; nt++)
            #pragma unroll
            for (int i = 0; i < 4; i++) acc[nt][i] = 0.f;

        const int am  = warp * 16;
        const int ar0 = min(am + r4, N_TOK - 1);
        const int ar1 = min(am + r4 + 8, N_TOK - 1);
        #pragma unroll
        for (int k8 = 0; k8 < 56; k8 += 8) {
            uint32_t af[4], bf[4][2];
            af[0] = __float_as_uint(Ss[ar0][k8 + c4    ]);
            af[1] = __float_as_uint(Ss[ar1][k8 + c4    ]);
            af[2] = __float_as_uint(Ss[ar0][k8 + c4 + 4]);
            af[3] = __float_as_uint(Ss[ar1][k8 + c4 + 4]);
            #pragma unroll
            for (int nt = 0; nt < 4; nt++) {
                bf[nt][0] = __float_as_uint(vt[nt * 8 + r4][k8 + c4    ]);
                bf[nt][1] = __float_as_uint(vt[nt * 8 + r4][k8 + c4 + 4]);
            }
            #pragma unroll
            for (int nt = 0; nt < 4; nt++)
                mma_tf32_16x8x8(acc[nt], af, bf[nt]);
        }
        float* aob = g_ao + (size_t)b * N_TOK * DIM + h * HD;
        const int n0 = am + r4, n1 = n0 + 8;
        #pragma unroll
        for (int nt = 0; nt < 4; nt++) {
            int col = nt * 8 + 2 * c4;
            if (n0 < N_TOK)
                *(float2*)(aob + (size_t)n0 * DIM + col) =
                    make_float2(to_tf32(acc[nt][0]), to_tf32(acc[nt][1]));
            if (n1 < N_TOK)
                *(float2*)(aob + (size_t)n1 * DIM + col) =
                    make_float2(to_tf32(acc[nt][2]), to_tf32(acc[nt][3]));
        }
    }
}

// ---------------------------------------------------------------------------
// launch
// ---------------------------------------------------------------------------
extern "C" void kernel_launch(void* const* d_in, const int* in_sizes, int n_in,
                              void* d_out, int out_size) {
    const float* x          = (const float*)d_in[0];
    const float* mask       = (const float*)d_in[1];
    const float* qkv_w      = (const float*)d_in[2];
    const float* qkv_b      = (const float*)d_in[3];
    const float* proj_w     = (const float*)d_in[4];
    const float* proj_b     = (const float*)d_in[5];
    const float* bias_table = (const float*)d_in[6];
    const int*   rel_index  = (const int*)d_in[7];
    float* out = (float*)d_out;

    void* p_qkv = nullptr; void* p_ao = nullptr;
    void* p_xr  = nullptr; void* p_wr = nullptr;
    cudaGetSymbolAddress(&p_qkv, g_qkv);
    cudaGetSymbolAddress(&p_ao,  g_ao);
    cudaGetSymbolAddress(&p_xr,  g_xr);
    cudaGetSymbolAddress(&p_wr,  g_wr);
    float* qkv = (float*)p_qkv;
    float* ao  = (float*)p_ao;
    float* xr  = (float*)p_xr;
    float* qkvw_r = (float*)p_wr;
    float* projw_r = qkvw_r + 3 * DIM * DIM;

    round_tf32_kernel<<<2048, 256>>>(x, xr, (T_TOT * DIM) / 4);
    round_tf32_kernel<<<256, 256>>>(qkv_w, qkvw_r, (3 * DIM * DIM) / 4);
    round_tf32_kernel<<<256, 256>>>(proj_w, projw_r, (DIM * DIM) / 4);
    {
        int n = H_HEADS * NW_MASK * NN;
        comb_kernel<<<(n + 255) / 256, 256>>>(bias_table, rel_index, mask);
    }
    {
        dim3 grid((3 * DIM) / GBN, T_TOT / GBM);
        gemm_tf32_pipe<<<grid, 256>>>(xr, qkvw_r, qkv_b, qkv, T_TOT, 3 * DIM, DIM);
    }
    {
        dim3 grid(H_HEADS, B_WIN);
        attn_fused_kernel<<<grid, 128>>>();
    }
    {
        dim3 grid(DIM / GBN, T_TOT / GBM);
        gemm_tf32_pipe<<<grid, 256>>>(ao, projw_r, proj_b, out, T_TOT, DIM, DIM);
    }
}

// round 9
// speedup vs baseline: 1.9464x; 1.0726x over previous
#include <cuda_runtime.h>
#include <cuda_bf16.h>
#include <cstdint>
#include <cstddef>

// ---------------------------------------------------------------------------
// WindowAttention (Swin-style): B_=4096 windows, N=49, C=384, H=12, hd=32
// Round 9: GEMM tile BM=128 x BN=128 (warp 32x64), 64KB dynamic SMEM,
//          2-stage cp.async + ldmatrix. Attention unchanged.
// ---------------------------------------------------------------------------

#define B_WIN   4096
#define N_TOK   49
#define DIM     384
#define H_HEADS 12
#define HD      32
#define T_TOT   (B_WIN * N_TOK)      // 200704 tokens
#define NW_MASK 64
#define NN      (N_TOK * N_TOK)      // 2401

__device__ float g_qkv[(size_t)T_TOT * 3 * DIM];   // (T, 1152)
__device__ float g_ao [(size_t)T_TOT * DIM];       // (T, 384) tf32-rounded
__device__ float g_xr [(size_t)T_TOT * DIM];       // x, tf32-rounded
__device__ float g_wr [3 * DIM * DIM + DIM * DIM]; // qkv_w | proj_w, rounded
__device__ float g_comb[(size_t)H_HEADS * NW_MASK * NN];  // bias+mask

// ---------------------------------------------------------------------------
// helpers
// ---------------------------------------------------------------------------
__device__ __forceinline__ float to_tf32(float x) {
    asm("cvt.rna.tf32.f32 %0, %0;" : "+f"(x));
    return x;
}

__device__ __forceinline__ void mma_tf32_16x8x8(float d[4], const uint32_t a[4],
                                                const uint32_t b[2]) {
    asm volatile(
        "mma.sync.aligned.m16n8k8.row.col.f32.tf32.tf32.f32 "
        "{%0,%1,%2,%3}, {%4,%5,%6,%7}, {%8,%9}, {%0,%1,%2,%3};\n"
        : "+f"(d[0]), "+f"(d[1]), "+f"(d[2]), "+f"(d[3])
        : "r"(a[0]), "r"(a[1]), "r"(a[2]), "r"(a[3]), "r"(b[0]), "r"(b[1]));
}

__device__ __forceinline__ void ldsm_x4(uint32_t& r0, uint32_t& r1,
                                        uint32_t& r2, uint32_t& r3, uint32_t addr) {
    asm volatile("ldmatrix.sync.aligned.m8n8.x4.shared.b16 {%0,%1,%2,%3}, [%4];\n"
                 : "=r"(r0), "=r"(r1), "=r"(r2), "=r"(r3) : "r"(addr));
}

__device__ __forceinline__ void cp_async16(uint32_t smem_addr, const void* gptr) {
    asm volatile("cp.async.cg.shared.global [%0], [%1], 16;\n"
                 :: "r"(smem_addr), "l"(gptr) : "memory");
}

// ---------------------------------------------------------------------------
// Kernel R: round fp32 -> tf32 (RNA), float4 grid-stride
// ---------------------------------------------------------------------------
__global__ void round_tf32_kernel(const float* __restrict__ src,
                                  float* __restrict__ dst, int n4) {
    int i = blockIdx.x * blockDim.x + threadIdx.x;
    int stride = gridDim.x * blockDim.x;
    for (; i < n4; i += stride) {
        float4 v = ((const float4*)src)[i];
        v.x = to_tf32(v.x); v.y = to_tf32(v.y);
        v.z = to_tf32(v.z); v.w = to_tf32(v.w);
        ((float4*)dst)[i] = v;
    }
}

// ---------------------------------------------------------------------------
// Kernel 0: comb[h][w][n][m] = bias_table[rel_index[n,m]][h] + mask[w][n][m]
// ---------------------------------------------------------------------------
__global__ void comb_kernel(const float* __restrict__ bias_table,
                            const int* __restrict__ rel_index,
                            const float* __restrict__ mask) {
    int idx = blockIdx.x * blockDim.x + threadIdx.x;
    if (idx < H_HEADS * NW_MASK * NN) {
        int h   = idx / (NW_MASK * NN);
        int rem = idx - h * (NW_MASK * NN);
        int w   = rem / NN;
        int nm  = rem - w * NN;
        g_comb[idx] = bias_table[rel_index[nm] * H_HEADS + h] + mask[w * NN + nm];
    }
}

// ---------------------------------------------------------------------------
// Kernel 1/3: pipelined TF32 GEMM  C[m,n] = sum_k A[m,k]*B[n,k] + bias[n]
//   A, B pre-rounded tf32. BM=128, BN=128, BK=32, 256 threads (8 warps 4x2),
//   warp tile 32x64. 2-stage cp.async; XOR-swizzled SMEM; ldmatrix loads.
//   Dynamic SMEM: 64 KB.
// ---------------------------------------------------------------------------
#define GBM 128
#define GBN 128
#define GBK 32
#define GEMM_SMEM_BYTES (4 * (2 * GBM * GBK + 2 * GBN * GBK))   // 65536

__global__ __launch_bounds__(256, 2)
void gemm_tf32_pipe(const float* __restrict__ A, const float* __restrict__ B,
                    const float* __restrict__ bias, float* __restrict__ C,
                    int M, int N, int K) {
    extern __shared__ float dynsmem[];
    float* As = dynsmem;                    // [2][GBM*GBK] 32 KB
    float* Bs = dynsmem + 2 * GBM * GBK;    // [2][GBN*GBK] 32 KB

    const int tid  = threadIdx.x;
    const int lane = tid & 31;
    const int warp = tid >> 5;
    const int wm   = warp >> 1;         // 0..3 (32 rows each)
    const int wn   = warp & 1;          // 0..1 (64 cols each)
    const int bm   = blockIdx.y * GBM;
    const int bn   = blockIdx.x * GBN;
    const int r4   = lane >> 2;
    const int c4   = lane & 3;

    const uint32_t as_base = (uint32_t)__cvta_generic_to_shared(As);
    const uint32_t bs_base = (uint32_t)__cvta_generic_to_shared(Bs);

    // cp.async loader geometry (A and B tiles both 128x32)
    const int lc4  = tid & 7;
    const int lrow = tid >> 3;
    const int pc4  = lc4 ^ (lrow & 7);

    // ldmatrix lane geometry
    const int l7       = lane & 7;
    const int a_half_m = (lane >> 3) & 1;
    const int a_half_k = lane >> 4;
    const int b_half_k = (lane >> 3) & 1;
    const int b_sel    = lane >> 4;

    int rA7[2]; uint32_t baseA[2];
    #pragma unroll
    for (int mt = 0; mt < 2; mt++) {
        int row = wm * 32 + mt * 16 + a_half_m * 8 + l7;
        rA7[mt]   = row & 7;
        baseA[mt] = (uint32_t)row * 128;
    }
    int rB7[4]; uint32_t baseB[4];
    #pragma unroll
    for (int j = 0; j < 4; j++) {
        int row = wn * 64 + (2 * j + b_sel) * 8 + l7;
        rB7[j]   = row & 7;
        baseB[j] = (uint32_t)row * 128;
    }

    const int kTiles = K / GBK;

    auto issue = [&](int ktf, int s) {
        #pragma unroll
        for (int i = 0; i < 4; i++) {
            int r = lrow + i * 32;
            cp_async16(as_base + (uint32_t)(s * (GBM * GBK) + r * GBK + pc4 * 4) * 4,
                       A + (size_t)(bm + r) * K + ktf + lc4 * 4);
        }
        #pragma unroll
        for (int i = 0; i < 4; i++) {
            int r = lrow + i * 32;
            cp_async16(bs_base + (uint32_t)(s * (GBN * GBK) + r * GBK + pc4 * 4) * 4,
                       B + (size_t)(bn + r) * K + ktf + lc4 * 4);
        }
        asm volatile("cp.async.commit_group;\n" ::: "memory");
    };

    float acc[2][8][4];
    #pragma unroll
    for (int mt = 0; mt < 2; mt++)
        #pragma unroll
        for (int nt = 0; nt < 8; nt++)
            #pragma unroll
            for (int i = 0; i < 4; i++) acc[mt][nt][i] = 0.f;

    issue(0, 0);

    for (int t = 0; t < kTiles; t++) {
        const int s = t & 1;
        if (t + 1 < kTiles) {
            issue((t + 1) * GBK, s ^ 1);
            asm volatile("cp.async.wait_group 1;\n" ::: "memory");
        } else {
            asm volatile("cp.async.wait_group 0;\n" ::: "memory");
        }
        __syncthreads();

        const uint32_t asb = as_base + (uint32_t)(s * (GBM * GBK)) * 4;
        const uint32_t bsb = bs_base + (uint32_t)(s * (GBN * GBK)) * 4;
        #pragma unroll
        for (int k8 = 0; k8 < GBK; k8 += 8) {
            const int kk = k8 >> 2;   // 0,2,4,6
            uint32_t af[2][4];
            uint32_t bf[8][2];
            #pragma unroll
            for (int mt = 0; mt < 2; mt++) {
                uint32_t addr = asb + baseA[mt] +
                                (uint32_t)(((kk + a_half_k) ^ rA7[mt]) << 4);
                ldsm_x4(af[mt][0], af[mt][1], af[mt][2], af[mt][3], addr);
            }
            #pragma unroll
            for (int j = 0; j < 4; j++) {
                uint32_t addr = bsb + baseB[j] +
                                (uint32_t)(((kk + b_half_k) ^ rB7[j]) << 4);
                ldsm_x4(bf[2 * j][0], bf[2 * j][1], bf[2 * j + 1][0], bf[2 * j + 1][1], addr);
            }
            #pragma unroll
            for (int mt = 0; mt < 2; mt++)
                #pragma unroll
                for (int nt = 0; nt < 8; nt++)
                    mma_tf32_16x8x8(acc[mt][nt], af[mt], bf[nt]);
        }
        __syncthreads();
    }

    // epilogue: add bias, store fp32
    #pragma unroll
    for (int mt = 0; mt < 2; mt++) {
        int row0 = bm + wm * 32 + mt * 16 + r4;
        #pragma unroll
        for (int nt = 0; nt < 8; nt++) {
            int col = bn + wn * 64 + nt * 8 + 2 * c4;
            float b0 = bias[col], b1 = bias[col + 1];
            float2 v01 = make_float2(acc[mt][nt][0] + b0, acc[mt][nt][1] + b1);
            float2 v23 = make_float2(acc[mt][nt][2] + b0, acc[mt][nt][3] + b1);
            *(float2*)(C + (size_t)row0 * N + col)       = v01;
            *(float2*)(C + (size_t)(row0 + 8) * N + col) = v23;
        }
    }
}

// ---------------------------------------------------------------------------
// Kernel 2: fused attention per (window, head), register-fused softmax
// ---------------------------------------------------------------------------
#define QS_STR 36
#define SS_STR 57

__global__ __launch_bounds__(128)
void attn_fused_kernel() {
    __shared__ float qs[N_TOK][QS_STR];
    __shared__ float ks[N_TOK][QS_STR];
    __shared__ float vt[HD][SS_STR];
    __shared__ float Ss[N_TOK][SS_STR];
    __shared__ float cb[2416];

    const int h    = blockIdx.x;
    const int b    = blockIdx.y;
    const int tid  = threadIdx.x;
    const int lane = tid & 31;
    const int warp = tid >> 5;
    const int r4   = lane >> 2;
    const int c4   = lane & 3;
    const float scale = 0.1767766952966369f;

    for (int i = tid; i < N_TOK * 8; i += 128) { int r = i >> 3; Ss[r][49 + (i & 7)] = 0.f; }
    for (int i = tid; i < HD * 8;    i += 128) { int r = i >> 3; vt[r][49 + (i & 7)] = 0.f; }

    const float* base = g_qkv + (size_t)b * N_TOK * (3 * DIM) + h * HD;
    #pragma unroll 4
    for (int idx = tid; idx < N_TOK * HD; idx += 128) {
        int n = idx >> 5;
        int d = idx & 31;
        const float* rp = base + (size_t)n * (3 * DIM) + d;
        qs[n][d] = to_tf32(rp[0] * scale);
        ks[n][d] = to_tf32(rp[DIM]);
        vt[d][n] = to_tf32(rp[2 * DIM]);
    }
    const float* cbg = g_comb + (size_t)(h * NW_MASK + (b & (NW_MASK - 1))) * NN;
    for (int i = tid; i < NN; i += 128) cb[i] = cbg[i];
    __syncthreads();

    {
        float acc[7][4];
        #pragma unroll
        for (int nt = 0; nt < 7; nt++)
            #pragma unroll
            for (int i = 0; i < 4; i++) acc[nt][i] = 0.f;

        const int am  = warp * 16;
        const int ar0 = min(am + r4, N_TOK - 1);
        const int ar1 = min(am + r4 + 8, N_TOK - 1);
        #pragma unroll
        for (int k8 = 0; k8 < 32; k8 += 8) {
            uint32_t af[4], bf[7][2];
            af[0] = __float_as_uint(qs[ar0][k8 + c4    ]);
            af[1] = __float_as_uint(qs[ar1][k8 + c4    ]);
            af[2] = __float_as_uint(qs[ar0][k8 + c4 + 4]);
            af[3] = __float_as_uint(qs[ar1][k8 + c4 + 4]);
            #pragma unroll
            for (int nt = 0; nt < 7; nt++) {
                int br = min(nt * 8 + r4, N_TOK - 1);
                bf[nt][0] = __float_as_uint(ks[br][k8 + c4    ]);
                bf[nt][1] = __float_as_uint(ks[br][k8 + c4 + 4]);
            }
            #pragma unroll
            for (int nt = 0; nt < 7; nt++)
                mma_tf32_16x8x8(acc[nt], af, bf[nt]);
        }

        const int n0  = am + r4;
        const int n1  = n0 + 8;
        const int cr0 = min(n0, N_TOK - 1) * N_TOK;
        const int cr1 = min(n1, N_TOK - 1) * N_TOK;
        float s0 = 0.f, s1 = 0.f;
        #pragma unroll
        for (int nt = 0; nt < 7; nt++) {
            int col0 = nt * 8 + 2 * c4;
            int col1 = col0 + 1;
            float e00 = (col0 < N_TOK) ? __expf(acc[nt][0] + cb[cr0 + col0]) : 0.f;
            float e01 = (col1 < N_TOK) ? __expf(acc[nt][1] + cb[cr0 + col1]) : 0.f;
            float e10 = (col0 < N_TOK) ? __expf(acc[nt][2] + cb[cr1 + col0]) : 0.f;
            float e11 = (col1 < N_TOK) ? __expf(acc[nt][3] + cb[cr1 + col1]) : 0.f;
            acc[nt][0] = e00; acc[nt][1] = e01; acc[nt][2] = e10; acc[nt][3] = e11;
            s0 += e00 + e01;
            s1 += e10 + e11;
        }
        s0 += __shfl_xor_sync(0xffffffffu, s0, 1);
        s0 += __shfl_xor_sync(0xffffffffu, s0, 2);
        s1 += __shfl_xor_sync(0xffffffffu, s1, 1);
        s1 += __shfl_xor_sync(0xffffffffu, s1, 2);
        float inv0 = __frcp_rn(s0);
        float inv1 = __frcp_rn(s1);

        #pragma unroll
        for (int nt = 0; nt < 7; nt++) {
            int col0 = nt * 8 + 2 * c4;
            int col1 = col0 + 1;
            if (n0 < N_TOK && col0 < N_TOK) Ss[n0][col0] = to_tf32(acc[nt][0] * inv0);
            if (n0 < N_TOK && col1 < N_TOK) Ss[n0][col1] = to_tf32(acc[nt][1] * inv0);
            if (n1 < N_TOK && col0 < N_TOK) Ss[n1][col0] = to_tf32(acc[nt][2] * inv1);
            if (n1 < N_TOK && col1 < N_TOK) Ss[n1][col1] = to_tf32(acc[nt][3] * inv1);
        }
    }
    __syncthreads();

    {
        float acc[4][4];
        #pragma unroll
        for (int nt = 0; nt < 4; nt++)
            #pragma unroll
            for (int i = 0; i < 4; i++) acc[nt][i] = 0.f;

        const int am  = warp * 16;
        const int ar0 = min(am + r4, N_TOK - 1);
        const int ar1 = min(am + r4 + 8, N_TOK - 1);
        #pragma unroll
        for (int k8 = 0; k8 < 56; k8 += 8) {
            uint32_t af[4], bf[4][2];
            af[0] = __float_as_uint(Ss[ar0][k8 + c4    ]);
            af[1] = __float_as_uint(Ss[ar1][k8 + c4    ]);
            af[2] = __float_as_uint(Ss[ar0][k8 + c4 + 4]);
            af[3] = __float_as_uint(Ss[ar1][k8 + c4 + 4]);
            #pragma unroll
            for (int nt = 0; nt < 4; nt++) {
                bf[nt][0] = __float_as_uint(vt[nt * 8 + r4][k8 + c4    ]);
                bf[nt][1] = __float_as_uint(vt[nt * 8 + r4][k8 + c4 + 4]);
            }
            #pragma unroll
            for (int nt = 0; nt < 4; nt++)
                mma_tf32_16x8x8(acc[nt], af, bf[nt]);
        }
        float* aob = g_ao + (size_t)b * N_TOK * DIM + h * HD;
        const int n0 = am + r4, n1 = n0 + 8;
        #pragma unroll
        for (int nt = 0; nt < 4; nt++) {
            int col = nt * 8 + 2 * c4;
            if (n0 < N_TOK)
                *(float2*)(aob + (size_t)n0 * DIM + col) =
                    make_float2(to_tf32(acc[nt][0]), to_tf32(acc[nt][1]));
            if (n1 < N_TOK)
                *(float2*)(aob + (size_t)n1 * DIM + col) =
                    make_float2(to_tf32(acc[nt][2]), to_tf32(acc[nt][3]));
        }
    }
}

// ---------------------------------------------------------------------------
// launch
// ---------------------------------------------------------------------------
extern "C" void kernel_launch(void* const* d_in, const int* in_sizes, int n_in,
                              void* d_out, int out_size) {
    const float* x          = (const float*)d_in[0];
    const float* mask       = (const float*)d_in[1];
    const float* qkv_w      = (const float*)d_in[2];
    const float* qkv_b      = (const float*)d_in[3];
    const float* proj_w     = (const float*)d_in[4];
    const float* proj_b     = (const float*)d_in[5];
    const float* bias_table = (const float*)d_in[6];
    const int*   rel_index  = (const int*)d_in[7];
    float* out = (float*)d_out;

    void* p_qkv = nullptr; void* p_ao = nullptr;
    void* p_xr  = nullptr; void* p_wr = nullptr;
    cudaGetSymbolAddress(&p_qkv, g_qkv);
    cudaGetSymbolAddress(&p_ao,  g_ao);
    cudaGetSymbolAddress(&p_xr,  g_xr);
    cudaGetSymbolAddress(&p_wr,  g_wr);
    float* qkv = (float*)p_qkv;
    float* ao  = (float*)p_ao;
    float* xr  = (float*)p_xr;
    float* qkvw_r = (float*)p_wr;
    float* projw_r = qkvw_r + 3 * DIM * DIM;

    cudaFuncSetAttribute(gemm_tf32_pipe,
                         cudaFuncAttributeMaxDynamicSharedMemorySize,
                         GEMM_SMEM_BYTES);

    round_tf32_kernel<<<2048, 256>>>(x, xr, (T_TOT * DIM) / 4);
    round_tf32_kernel<<<256, 256>>>(qkv_w, qkvw_r, (3 * DIM * DIM) / 4);
    round_tf32_kernel<<<256, 256>>>(proj_w, projw_r, (DIM * DIM) / 4);
    {
        int n = H_HEADS * NW_MASK * NN;
        comb_kernel<<<(n + 255) / 256, 256>>>(bias_table, rel_index, mask);
    }
    // 1) QKV GEMM: (T,384) @ (1152,384)^T -> (T,1152)
    {
        dim3 grid((3 * DIM) / GBN, T_TOT / GBM);
        gemm_tf32_pipe<<<grid, 256, GEMM_SMEM_BYTES>>>(xr, qkvw_r, qkv_b, qkv,
                                                       T_TOT, 3 * DIM, DIM);
    }
    // 2) fused attention
    {
        dim3 grid(H_HEADS, B_WIN);
        attn_fused_kernel<<<grid, 128>>>();
    }
    // 3) proj GEMM: (T,384) @ (384,384)^T -> (T,384)
    {
        dim3 grid(DIM / GBN, T_TOT / GBM);
        gemm_tf32_pipe<<<grid, 256, GEMM_SMEM_BYTES>>>(ao, projw_r, proj_b, out,
                                                       T_TOT, DIM, DIM);
    }
}